// round 1
// baseline (speedup 1.0000x reference)
#include <cuda_runtime.h>
#include <math.h>

#define NNODES 20000
#define NEDGES 320000
#define HD 128
#define OUT_OE (NNODES * HD)   // n_out occupies [0, 2560000); oE follows

// ---------------- scratch (device globals; no allocations allowed) ----------
__device__ float g_Q[NNODES * HD];
__device__ float g_K[NNODES * HD];
__device__ float g_V[NNODES * HD];
__device__ float g_a[NEDGES * 8];
__device__ int   g_deg[NNODES];
__device__ int   g_off[NNODES + 1];
__device__ int   g_cursor[NNODES];
__device__ int   g_csr_e[NEDGES];
__device__ int   g_csr_src[NEDGES];

// ---------------- K1: QKV node GEMM  [20000,64] @ [64,128] x3 ---------------
// BM=128, BN=64, full K=64 in smem. 128 threads, 8x8 register tile each.
__global__ __launch_bounds__(128) void qkv_kernel(
    const float* __restrict__ x,
    const float* __restrict__ Qw, const float* __restrict__ Qb,
    const float* __restrict__ Kw, const float* __restrict__ Kb,
    const float* __restrict__ Vw, const float* __restrict__ Vb)
{
    __shared__ float As[128][64];
    __shared__ float Bs[64][64];
    const int t  = threadIdx.x;
    const int bx = blockIdx.x;
    const int j  = blockIdx.y;          // 0..5 : {Q0,Q1,K0,K1,V0,V1}
    const int sel = j >> 1;
    const float* W  = (sel == 0) ? Qw : ((sel == 1) ? Kw : Vw);
    const float* Bv = (sel == 0) ? Qb : ((sel == 1) ? Kb : Vb);
    float* out      = (sel == 0) ? g_Q : ((sel == 1) ? g_K : g_V);
    const int col0 = (j & 1) * 64;
    const int m0   = bx * 128;

    // load A tile (guarded, zero-pad past NNODES)
    #pragma unroll
    for (int l = 0; l < 16; l++) {
        int idx = l * 128 + t;          // float4 slot
        int m  = idx >> 4;
        int k4 = (idx & 15) * 4;
        float4 v = make_float4(0.f, 0.f, 0.f, 0.f);
        if (m0 + m < NNODES) v = *(const float4*)(x + (size_t)(m0 + m) * 64 + k4);
        *(float4*)&As[m][k4] = v;
    }
    // load B tile
    #pragma unroll
    for (int l = 0; l < 8; l++) {
        int idx = l * 128 + t;
        int k  = idx >> 4;
        int n4 = (idx & 15) * 4;
        *(float4*)&Bs[k][n4] = *(const float4*)(W + (size_t)k * HD + col0 + n4);
    }
    __syncthreads();

    const int tx = t & 7, ty = t >> 3;
    float acc[8][8];
    #pragma unroll
    for (int i = 0; i < 8; i++)
        #pragma unroll
        for (int jj = 0; jj < 8; jj++) acc[i][jj] = 0.f;

    #pragma unroll 4
    for (int k = 0; k < 64; k++) {
        float4 b0 = *(const float4*)&Bs[k][tx * 8];
        float4 b1 = *(const float4*)&Bs[k][tx * 8 + 4];
        #pragma unroll
        for (int i = 0; i < 8; i++) {
            float a = As[ty * 8 + i][k];
            acc[i][0] += a * b0.x; acc[i][1] += a * b0.y;
            acc[i][2] += a * b0.z; acc[i][3] += a * b0.w;
            acc[i][4] += a * b1.x; acc[i][5] += a * b1.y;
            acc[i][6] += a * b1.z; acc[i][7] += a * b1.w;
        }
    }

    float4 bias0 = *(const float4*)(Bv + col0 + tx * 8);
    float4 bias1 = *(const float4*)(Bv + col0 + tx * 8 + 4);
    #pragma unroll
    for (int i = 0; i < 8; i++) {
        int gm = m0 + ty * 8 + i;
        if (gm < NNODES) {
            float4 o0 = make_float4(acc[i][0] + bias0.x, acc[i][1] + bias0.y,
                                    acc[i][2] + bias0.z, acc[i][3] + bias0.w);
            float4 o1 = make_float4(acc[i][4] + bias1.x, acc[i][5] + bias1.y,
                                    acc[i][6] + bias1.z, acc[i][7] + bias1.w);
            *(float4*)(out + (size_t)gm * HD + col0 + tx * 8)     = o0;
            *(float4*)(out + (size_t)gm * HD + col0 + tx * 8 + 4) = o1;
        }
    }
}

// ---------------- K2: edge GEMM + fused score epilogue ----------------------
// E = edge_attr @ Ew  ([320000,64]@[64,256]); BN=64 covers 2 heads (32 cols/head).
// Epilogue: s2 = Ex1*Ex2; score = K[src]+Q[dst]+sign(s2)*sqrt(|s2|); write oE;
// a = clamp(sum_d score*Aw, +-5) -> g_a.
__global__ __launch_bounds__(128) void edge_kernel(
    const float* __restrict__ eattr, const int* __restrict__ eidx,
    const float* __restrict__ Ew, const float* __restrict__ Eb,
    const float* __restrict__ Aw, float* __restrict__ outbuf)
{
    __shared__ float As[128][64];    // reused as E-tile after compute
    __shared__ float Bs[64][64];
    const int t  = threadIdx.x;
    const int m0 = blockIdx.x * 128; // NEDGES % 128 == 0, no guards
    const int jb = blockIdx.y;       // 0..3
    const int n0 = jb * 64;

    #pragma unroll
    for (int l = 0; l < 16; l++) {
        int idx = l * 128 + t;
        int m  = idx >> 4;
        int k4 = (idx & 15) * 4;
        *(float4*)&As[m][k4] = *(const float4*)(eattr + (size_t)(m0 + m) * 64 + k4);
    }
    #pragma unroll
    for (int l = 0; l < 8; l++) {
        int idx = l * 128 + t;
        int k  = idx >> 4;
        int n4 = (idx & 15) * 4;
        *(float4*)&Bs[k][n4] = *(const float4*)(Ew + (size_t)k * 256 + n0 + n4);
    }
    __syncthreads();

    const int tx = t & 7, ty = t >> 3;
    float acc[8][8];
    #pragma unroll
    for (int i = 0; i < 8; i++)
        #pragma unroll
        for (int jj = 0; jj < 8; jj++) acc[i][jj] = 0.f;

    #pragma unroll 4
    for (int k = 0; k < 64; k++) {
        float4 b0 = *(const float4*)&Bs[k][tx * 8];
        float4 b1 = *(const float4*)&Bs[k][tx * 8 + 4];
        #pragma unroll
        for (int i = 0; i < 8; i++) {
            float a = As[ty * 8 + i][k];
            acc[i][0] += a * b0.x; acc[i][1] += a * b0.y;
            acc[i][2] += a * b0.z; acc[i][3] += a * b0.w;
            acc[i][4] += a * b1.x; acc[i][5] += a * b1.y;
            acc[i][6] += a * b1.z; acc[i][7] += a * b1.w;
        }
    }
    __syncthreads();                 // everyone done reading As
    #pragma unroll
    for (int i = 0; i < 8; i++) {
        *(float4*)&As[ty * 8 + i][tx * 8]     = *(float4*)&acc[i][0];
        *(float4*)&As[ty * 8 + i][tx * 8 + 4] = *(float4*)&acc[i][4];
    }
    __syncthreads();

    // Epilogue: 32 lanes per edge (2 heads x 16 dims); 4 edges per pass.
    const int lane = t & 31;
    const int hh = lane >> 4;        // which head within this tile
    const int dd = lane & 15;        // dim
    const int h  = jb * 2 + hh;      // global head
    const float aw  = Aw[dd * 8 + h];
    const float eb1 = Eb[n0 + hh * 32 + dd];
    const float eb2 = Eb[n0 + hh * 32 + 16 + dd];

    for (int ep = 0; ep < 32; ep++) {
        int el = ep * 4 + (t >> 5);
        int e  = m0 + el;
        float s1 = As[el][hh * 32 + dd] + eb1;
        float s2 = As[el][hh * 32 + 16 + dd] + eb2;
        float p  = s1 * s2;
        float r  = sqrtf(fabsf(p));
        float sc = (p >= 0.f) ? r : -r;
        int src = eidx[e];
        int dst = eidx[NEDGES + e];
        sc += g_K[(size_t)src * HD + h * 16 + dd] + g_Q[(size_t)dst * HD + h * 16 + dd];
        outbuf[(size_t)OUT_OE + (size_t)e * HD + h * 16 + dd] = sc;

        float av = sc * aw;
        av += __shfl_xor_sync(0xffffffffu, av, 8);
        av += __shfl_xor_sync(0xffffffffu, av, 4);
        av += __shfl_xor_sync(0xffffffffu, av, 2);
        av += __shfl_xor_sync(0xffffffffu, av, 1);
        if (dd == 0) {
            av = fminf(fmaxf(av, -5.0f), 5.0f);
            g_a[(size_t)e * 8 + h] = av;
        }
    }
}

// ---------------- K3: CSR build ---------------------------------------------
__global__ void zero_kernel()
{
    int i = blockIdx.x * blockDim.x + threadIdx.x;
    if (i < NNODES) g_deg[i] = 0;
}

__global__ void hist_kernel(const int* __restrict__ eidx)
{
    int e = blockIdx.x * blockDim.x + threadIdx.x;
    if (e < NEDGES) atomicAdd(&g_deg[eidx[NEDGES + e]], 1);
}

__global__ void scan_kernel()
{
    __shared__ int s[1024];
    __shared__ int carry_s;
    const int t = threadIdx.x;
    if (t == 0) carry_s = 0;
    __syncthreads();
    for (int base = 0; base < NNODES; base += 1024) {
        int idx = base + t;
        int v = (idx < NNODES) ? g_deg[idx] : 0;
        s[t] = v;
        __syncthreads();
        for (int off = 1; off < 1024; off <<= 1) {
            int xv = 0;
            if (t >= off) xv = s[t - off];
            __syncthreads();
            s[t] += xv;
            __syncthreads();
        }
        int excl = s[t] - v + carry_s;
        if (idx < NNODES) { g_off[idx] = excl; g_cursor[idx] = excl; }
        __syncthreads();
        if (t == 0) carry_s += s[1023];
        __syncthreads();
    }
    if (t == 0) g_off[NNODES] = carry_s;
}

__global__ void scatter_kernel(const int* __restrict__ eidx)
{
    int e = blockIdx.x * blockDim.x + threadIdx.x;
    if (e < NEDGES) {
        int dst = eidx[NEDGES + e];
        int p = atomicAdd(&g_cursor[dst], 1);
        g_csr_e[p]   = e;
        g_csr_src[p] = eidx[e];
    }
}

// ---------------- K4: fused softmax + aggregation (node-parallel) ----------
// One block (128 threads) per node; thread = (h, c). Two passes over the
// node's incoming edges: max, then exp-weighted sums; divide at the end.
__global__ __launch_bounds__(128) void node_kernel(
    const float* __restrict__ VeRow,
    const float* __restrict__ oE,      // = outbuf + OUT_OE
    float* __restrict__ n_out)
{
    const int n = blockIdx.x;
    const int t = threadIdx.x;
    const int h = t >> 4, c = t & 15;
    const int beg = g_off[n], end = g_off[n + 1];

    float m = -1e30f;
    for (int i = beg; i < end; i++) {
        int e = g_csr_e[i];
        m = fmaxf(m, g_a[(size_t)e * 8 + h]);
    }
    float den = 0.f, accV = 0.f, accR = 0.f;
    for (int i = beg; i < end; i++) {
        int e   = g_csr_e[i];
        int src = g_csr_src[i];
        float w = expf(g_a[(size_t)e * 8 + h] - m);
        den  += w;
        accV += w * g_V[(size_t)src * HD + h * 16 + c];
        accR += w * oE[(size_t)e * HD + h * 16 + c];
    }
    float inv = 1.f / (den + 1e-16f);

    __shared__ float rowS[8][17];
    rowS[h][c] = accR * inv;
    __syncthreads();
    float r = 0.f;
    #pragma unroll
    for (int d = 0; d < 16; d++)
        r += rowS[h][d] * VeRow[d * HD + h * 16 + c];

    n_out[(size_t)n * HD + t] = accV * inv + r;
}

// ---------------- launch -----------------------------------------------------
extern "C" void kernel_launch(void* const* d_in, const int* in_sizes, int n_in,
                              void* d_out, int out_size)
{
    const float* x     = (const float*)d_in[0];
    const float* eattr = (const float*)d_in[1];
    const int*   eidx  = (const int*)  d_in[2];
    const float* Qw = (const float*)d_in[3];  const float* Qb = (const float*)d_in[4];
    const float* Kw = (const float*)d_in[5];  const float* Kb = (const float*)d_in[6];
    const float* Ew = (const float*)d_in[7];  const float* Eb = (const float*)d_in[8];
    const float* Vw = (const float*)d_in[9];  const float* Vb = (const float*)d_in[10];
    const float* Aw = (const float*)d_in[11]; const float* VeRow = (const float*)d_in[12];
    float* out = (float*)d_out;

    zero_kernel<<<(NNODES + 255) / 256, 256>>>();
    qkv_kernel<<<dim3((NNODES + 127) / 128, 6), 128>>>(x, Qw, Qb, Kw, Kb, Vw, Vb);
    edge_kernel<<<dim3(NEDGES / 128, 4), 128>>>(eattr, eidx, Ew, Eb, Aw, out);
    hist_kernel<<<(NEDGES + 255) / 256, 256>>>(eidx);
    scan_kernel<<<1, 1024>>>();
    scatter_kernel<<<(NEDGES + 255) / 256, 256>>>(eidx);
    node_kernel<<<NNODES, 128>>>(VeRow, out + OUT_OE, out);
}

// round 2
// speedup vs baseline: 1.0132x; 1.0132x over previous
#include <cuda_runtime.h>
#include <math.h>

#define NNODES 20000
#define NEDGES 320000
#define HD 128
#define OUT_OE (NNODES * HD)   // n_out occupies [0, 2560000); oE follows

// ---------------- scratch (device globals; no allocations allowed) ----------
__device__ float g_Q[NNODES * HD];
__device__ float g_K[NNODES * HD];
__device__ float g_V[NNODES * HD];
__device__ float g_w[NEDGES * 8];       // exp(clamp(a)) per (edge, head)
__device__ int   g_deg[NNODES];
__device__ int   g_off[NNODES + 1];
__device__ int   g_cursor[NNODES];
__device__ int2  g_csr[NEDGES];         // {edge id, src}

// ---------------- K1: QKV node GEMM  [20000,64] @ [64,128] x3 ---------------
// BM=64, BN=128 (full output width), 128 threads, 8x8 register tile.
// A stored transposed + XOR-swizzled for conflict-free LDS.128 reads.
__global__ __launch_bounds__(128) void qkv_kernel(
    const float* __restrict__ x,
    const float* __restrict__ Qw, const float* __restrict__ Qb,
    const float* __restrict__ Kw, const float* __restrict__ Kb,
    const float* __restrict__ Vw, const float* __restrict__ Vb)
{
    __shared__ float As[64][64];    // As[k][m ^ ((k&7)<<3)]
    __shared__ float Bs[64][128];
    const int t   = threadIdx.x;
    const int m0  = blockIdx.x * 64;
    const int sel = blockIdx.y;     // 0=Q,1=K,2=V
    const float* W  = (sel == 0) ? Qw : ((sel == 1) ? Kw : Vw);
    const float* Bv = (sel == 0) ? Qb : ((sel == 1) ? Kb : Vb);
    float* out      = (sel == 0) ? g_Q : ((sel == 1) ? g_K : g_V);

    // A tile: 64x64, transposed store with swizzle (guarded rows)
    #pragma unroll
    for (int l = 0; l < 8; l++) {
        int idx = l * 128 + t;
        int m  = idx >> 4;
        int k4 = (idx & 15) * 4;
        float4 v = make_float4(0.f, 0.f, 0.f, 0.f);
        if (m0 + m < NNODES) v = *(const float4*)(x + (size_t)(m0 + m) * 64 + k4);
        As[k4 + 0][m ^ (((k4 + 0) & 7) << 3)] = v.x;
        As[k4 + 1][m ^ (((k4 + 1) & 7) << 3)] = v.y;
        As[k4 + 2][m ^ (((k4 + 2) & 7) << 3)] = v.z;
        As[k4 + 3][m ^ (((k4 + 3) & 7) << 3)] = v.w;
    }
    // B tile 64x128
    #pragma unroll
    for (int l = 0; l < 16; l++) {
        int idx = l * 128 + t;
        int k  = idx >> 5;
        int n4 = (idx & 31) * 4;
        *(float4*)&Bs[k][n4] = *(const float4*)(W + (size_t)k * HD + n4);
    }
    __syncthreads();

    const int tx = t & 15, ty = t >> 4;
    float acc[8][8];
    #pragma unroll
    for (int i = 0; i < 8; i++)
        #pragma unroll
        for (int j = 0; j < 8; j++) acc[i][j] = 0.f;

    #pragma unroll 4
    for (int k = 0; k < 64; k++) {
        int ar = ((ty ^ (k & 7)) << 3);
        float4 a0 = *(const float4*)&As[k][ar];
        float4 a1 = *(const float4*)&As[k][ar + 4];
        float4 b0 = *(const float4*)&Bs[k][tx * 8];
        float4 b1 = *(const float4*)&Bs[k][tx * 8 + 4];
        float av[8] = {a0.x, a0.y, a0.z, a0.w, a1.x, a1.y, a1.z, a1.w};
        #pragma unroll
        for (int i = 0; i < 8; i++) {
            acc[i][0] += av[i] * b0.x; acc[i][1] += av[i] * b0.y;
            acc[i][2] += av[i] * b0.z; acc[i][3] += av[i] * b0.w;
            acc[i][4] += av[i] * b1.x; acc[i][5] += av[i] * b1.y;
            acc[i][6] += av[i] * b1.z; acc[i][7] += av[i] * b1.w;
        }
    }

    float4 bias0 = *(const float4*)(Bv + tx * 8);
    float4 bias1 = *(const float4*)(Bv + tx * 8 + 4);
    #pragma unroll
    for (int i = 0; i < 8; i++) {
        int gm = m0 + ty * 8 + i;
        if (gm < NNODES) {
            float4 o0 = make_float4(acc[i][0] + bias0.x, acc[i][1] + bias0.y,
                                    acc[i][2] + bias0.z, acc[i][3] + bias0.w);
            float4 o1 = make_float4(acc[i][4] + bias1.x, acc[i][5] + bias1.y,
                                    acc[i][6] + bias1.z, acc[i][7] + bias1.w);
            *(float4*)(out + (size_t)gm * HD + tx * 8)     = o0;
            *(float4*)(out + (size_t)gm * HD + tx * 8 + 4) = o1;
        }
    }
}

// ---------------- K2: edge GEMM + fused score epilogue ----------------------
// E = edge_attr @ Ew  ([320000,64]@[64,256]); BM=64 edges, BN=128 (4 heads).
// Epilogue computes score, writes oE, and w = exp(clamp(score . Aw)).
__global__ __launch_bounds__(128) void edge_kernel(
    const float* __restrict__ eattr, const int* __restrict__ eidx,
    const float* __restrict__ Ew, const float* __restrict__ Eb,
    const float* __restrict__ Aw, float* __restrict__ outbuf)
{
    __shared__ float As[64][64];    // transposed + swizzled
    __shared__ float Bs[64][128];   // B tile, then reused as E-result tile
    const int t  = threadIdx.x;
    const int m0 = blockIdx.x * 64;   // NEDGES % 64 == 0
    const int jb = blockIdx.y;        // 0..1
    const int n0 = jb * 128;

    #pragma unroll
    for (int l = 0; l < 8; l++) {
        int idx = l * 128 + t;
        int m  = idx >> 4;
        int k4 = (idx & 15) * 4;
        float4 v = *(const float4*)(eattr + (size_t)(m0 + m) * 64 + k4);
        As[k4 + 0][m ^ (((k4 + 0) & 7) << 3)] = v.x;
        As[k4 + 1][m ^ (((k4 + 1) & 7) << 3)] = v.y;
        As[k4 + 2][m ^ (((k4 + 2) & 7) << 3)] = v.z;
        As[k4 + 3][m ^ (((k4 + 3) & 7) << 3)] = v.w;
    }
    #pragma unroll
    for (int l = 0; l < 16; l++) {
        int idx = l * 128 + t;
        int k  = idx >> 5;
        int n4 = (idx & 31) * 4;
        *(float4*)&Bs[k][n4] = *(const float4*)(Ew + (size_t)k * 256 + n0 + n4);
    }
    __syncthreads();

    const int tx = t & 15, ty = t >> 4;
    float acc[8][8];
    #pragma unroll
    for (int i = 0; i < 8; i++)
        #pragma unroll
        for (int j = 0; j < 8; j++) acc[i][j] = 0.f;

    #pragma unroll 4
    for (int k = 0; k < 64; k++) {
        int ar = ((ty ^ (k & 7)) << 3);
        float4 a0 = *(const float4*)&As[k][ar];
        float4 a1 = *(const float4*)&As[k][ar + 4];
        float4 b0 = *(const float4*)&Bs[k][tx * 8];
        float4 b1 = *(const float4*)&Bs[k][tx * 8 + 4];
        float av[8] = {a0.x, a0.y, a0.z, a0.w, a1.x, a1.y, a1.z, a1.w};
        #pragma unroll
        for (int i = 0; i < 8; i++) {
            acc[i][0] += av[i] * b0.x; acc[i][1] += av[i] * b0.y;
            acc[i][2] += av[i] * b0.z; acc[i][3] += av[i] * b0.w;
            acc[i][4] += av[i] * b1.x; acc[i][5] += av[i] * b1.y;
            acc[i][6] += av[i] * b1.z; acc[i][7] += av[i] * b1.w;
        }
    }
    __syncthreads();                 // B reads done; reuse Bs as E-tile
    #pragma unroll
    for (int i = 0; i < 8; i++) {
        *(float4*)&Bs[ty * 8 + i][tx * 8]     = *(float4*)&acc[i][0];
        *(float4*)&Bs[ty * 8 + i][tx * 8 + 4] = *(float4*)&acc[i][4];
    }
    __syncthreads();

    // Epilogue: 64 lanes per edge (4 heads x 16 dims); 2 edges per pass.
    const int sub  = t >> 6;
    const int lane = t & 63;
    const int hl   = lane >> 4;
    const int d    = lane & 15;
    const int h    = jb * 4 + hl;
    const float eb1 = Eb[n0 + hl * 32 + d];
    const float eb2 = Eb[n0 + hl * 32 + 16 + d];
    const float aw  = Aw[d * 8 + h];
    const int col   = jb * 64 + lane;

    #pragma unroll 4
    for (int ep = 0; ep < 32; ep++) {
        int el = ep * 2 + sub;
        int e  = m0 + el;
        float s1 = Bs[el][hl * 32 + d] + eb1;
        float s2 = Bs[el][hl * 32 + 16 + d] + eb2;
        float p  = s1 * s2;
        float r  = sqrtf(fabsf(p));
        float sc = (p >= 0.f) ? r : -r;
        int src = eidx[e];
        int dst = eidx[NEDGES + e];
        sc += g_K[(size_t)src * HD + col] + g_Q[(size_t)dst * HD + col];
        outbuf[(size_t)OUT_OE + (size_t)e * HD + col] = sc;

        float av = sc * aw;
        av += __shfl_xor_sync(0xffffffffu, av, 8);
        av += __shfl_xor_sync(0xffffffffu, av, 4);
        av += __shfl_xor_sync(0xffffffffu, av, 2);
        av += __shfl_xor_sync(0xffffffffu, av, 1);
        if (d == 0) {
            av = fminf(fmaxf(av, -5.0f), 5.0f);
            g_w[(size_t)e * 8 + h] = expf(av);
        }
    }
}

// ---------------- K3: CSR build ---------------------------------------------
__global__ void zero_kernel()
{
    int i = blockIdx.x * blockDim.x + threadIdx.x;
    if (i < NNODES) g_deg[i] = 0;
}

__global__ void hist_kernel(const int* __restrict__ eidx)
{
    int e = blockIdx.x * blockDim.x + threadIdx.x;
    if (e < NEDGES) atomicAdd(&g_deg[eidx[NEDGES + e]], 1);
}

__global__ void scan_kernel()
{
    __shared__ int s[1024];
    __shared__ int carry_s;
    const int t = threadIdx.x;
    if (t == 0) carry_s = 0;
    __syncthreads();
    for (int base = 0; base < NNODES; base += 1024) {
        int idx = base + t;
        int v = (idx < NNODES) ? g_deg[idx] : 0;
        s[t] = v;
        __syncthreads();
        for (int off = 1; off < 1024; off <<= 1) {
            int xv = 0;
            if (t >= off) xv = s[t - off];
            __syncthreads();
            s[t] += xv;
            __syncthreads();
        }
        int excl = s[t] - v + carry_s;
        if (idx < NNODES) { g_off[idx] = excl; g_cursor[idx] = excl; }
        __syncthreads();
        if (t == 0) carry_s += s[1023];
        __syncthreads();
    }
    if (t == 0) g_off[NNODES] = carry_s;
}

__global__ void scatter_kernel(const int* __restrict__ eidx)
{
    int e = blockIdx.x * blockDim.x + threadIdx.x;
    if (e < NEDGES) {
        int dst = eidx[NEDGES + e];
        int p = atomicAdd(&g_cursor[dst], 1);
        g_csr[p] = make_int2(e, eidx[e]);
    }
}

// ---------------- K4: fused softmax + aggregation (node-parallel) ----------
// One block (128 threads) per node; thread = (h, c). Single pass (no max:
// a is clamped to [-5,5] so exp cannot overflow; softmax is shift-invariant).
__global__ __launch_bounds__(128) void node_kernel(
    const float* __restrict__ VeRow,
    const float* __restrict__ oE,
    float* __restrict__ n_out)
{
    __shared__ int2  stage[128];
    __shared__ float rowS[8][17];
    const int n = blockIdx.x;
    const int t = threadIdx.x;
    const int h = t >> 4, c = t & 15;
    const int beg = g_off[n], end = g_off[n + 1];

    float den = 0.f, accV = 0.f, accR = 0.f;
    for (int base = beg; base < end; base += 128) {
        int cnt = min(128, end - base);
        __syncthreads();
        if (t < cnt) stage[t] = g_csr[base + t];
        __syncthreads();
        #pragma unroll 4
        for (int i = 0; i < cnt; i++) {
            int e   = stage[i].x;
            int src = stage[i].y;
            float w = g_w[(size_t)e * 8 + h];
            den  += w;
            accV += w * g_V[(size_t)src * HD + t];
            accR += w * oE[(size_t)e * HD + t];
        }
    }
    float inv = 1.f / (den + 1e-16f);

    rowS[h][c] = accR * inv;
    __syncthreads();
    float r = 0.f;
    #pragma unroll
    for (int d = 0; d < 16; d++)
        r += rowS[h][d] * VeRow[d * HD + h * 16 + c];

    n_out[(size_t)n * HD + t] = accV * inv + r;
}

// ---------------- launch -----------------------------------------------------
extern "C" void kernel_launch(void* const* d_in, const int* in_sizes, int n_in,
                              void* d_out, int out_size)
{
    const float* x     = (const float*)d_in[0];
    const float* eattr = (const float*)d_in[1];
    const int*   eidx  = (const int*)  d_in[2];
    const float* Qw = (const float*)d_in[3];  const float* Qb = (const float*)d_in[4];
    const float* Kw = (const float*)d_in[5];  const float* Kb = (const float*)d_in[6];
    const float* Ew = (const float*)d_in[7];  const float* Eb = (const float*)d_in[8];
    const float* Vw = (const float*)d_in[9];  const float* Vb = (const float*)d_in[10];
    const float* Aw = (const float*)d_in[11]; const float* VeRow = (const float*)d_in[12];
    float* out = (float*)d_out;

    zero_kernel<<<(NNODES + 255) / 256, 256>>>();
    hist_kernel<<<(NEDGES + 255) / 256, 256>>>(eidx);
    scan_kernel<<<1, 1024>>>();
    scatter_kernel<<<(NEDGES + 255) / 256, 256>>>(eidx);
    qkv_kernel<<<dim3((NNODES + 63) / 64, 3), 128>>>(x, Qw, Qb, Kw, Kb, Vw, Vb);
    edge_kernel<<<dim3(NEDGES / 64, 2), 128>>>(eattr, eidx, Ew, Eb, Aw, out);
    node_kernel<<<NNODES, 128>>>(VeRow, out + OUT_OE, out);
}

// round 4
// speedup vs baseline: 1.4671x; 1.4480x over previous
#include <cuda_runtime.h>
#include <cuda_bf16.h>
#include <math.h>
#include <stdint.h>

#define NNODES 20000
#define NEDGES 320000
#define HD 128
#define OUT_OE (NNODES * HD)

// ---------------- scratch ----------------------------------------------------
__device__ float g_Q[NNODES * HD];
__device__ float g_K[NNODES * HD];
__device__ float g_V[NNODES * HD];
__device__ float g_w[NEDGES * 8];
__device__ int   g_deg[NNODES];
__device__ int   g_off[NNODES + 1];
__device__ int   g_cursor[NNODES];
__device__ int2  g_csr[NEDGES];
// pre-swizzled bf16 B images: [2 halves][64 k][128 n], 16KB per half per img
__device__ unsigned long long g_Bh[4096];
__device__ unsigned long long g_Bl[4096];

// ---------------- helpers ----------------------------------------------------
__device__ __forceinline__ uint32_t smem_u32(const void* p) {
    uint32_t a;
    asm("{ .reg .u64 t; cvta.to.shared.u64 t, %1; cvt.u32.u64 %0, t; }" : "=r"(a) : "l"(p));
    return a;
}
__device__ __forceinline__ unsigned long long pack4_hi(float4 v) {
    unsigned short h0 = __bfloat16_as_ushort(__float2bfloat16(v.x));
    unsigned short h1 = __bfloat16_as_ushort(__float2bfloat16(v.y));
    unsigned short h2 = __bfloat16_as_ushort(__float2bfloat16(v.z));
    unsigned short h3 = __bfloat16_as_ushort(__float2bfloat16(v.w));
    return (unsigned long long)h0 | ((unsigned long long)h1 << 16) |
           ((unsigned long long)h2 << 32) | ((unsigned long long)h3 << 48);
}
__device__ __forceinline__ float4 resid4(float4 v) {
    return make_float4(
        v.x - __bfloat162float(__float2bfloat16(v.x)),
        v.y - __bfloat162float(__float2bfloat16(v.y)),
        v.z - __bfloat162float(__float2bfloat16(v.z)),
        v.w - __bfloat162float(__float2bfloat16(v.w)));
}
__device__ __forceinline__ void ldmatrix_x4(uint32_t* r, uint32_t addr) {
    asm volatile("ldmatrix.sync.aligned.m8n8.x4.shared.b16 {%0,%1,%2,%3}, [%4];"
                 : "=r"(r[0]), "=r"(r[1]), "=r"(r[2]), "=r"(r[3]) : "r"(addr));
}
__device__ __forceinline__ void ldmatrix_x2t(uint32_t* r, uint32_t addr) {
    asm volatile("ldmatrix.sync.aligned.m8n8.x2.trans.shared.b16 {%0,%1}, [%2];"
                 : "=r"(r[0]), "=r"(r[1]) : "r"(addr));
}
__device__ __forceinline__ void mma16816(float* c, const uint32_t* a, const uint32_t* b) {
    asm volatile(
        "mma.sync.aligned.m16n8k16.row.col.f32.bf16.bf16.f32 "
        "{%0,%1,%2,%3}, {%4,%5,%6,%7}, {%8,%9}, {%0,%1,%2,%3};"
        : "+f"(c[0]), "+f"(c[1]), "+f"(c[2]), "+f"(c[3])
        : "r"(a[0]), "r"(a[1]), "r"(a[2]), "r"(a[3]), "r"(b[0]), "r"(b[1]));
}

// ---------------- K0: precompute bf16 hi/lo images of Ew --------------------
// Layout per half jb: rows k (0..63) of 128 n bf16 (256B), 16B chunk at
// byte = k*256 + ((n*2) ^ ((k&7)<<4)).
__global__ void bprep_kernel(const float* __restrict__ Ew)
{
    const int jb = blockIdx.x;
    const int t  = threadIdx.x;   // 256
    for (int it = 0; it < 8; it++) {
        int idx = it * 256 + t;          // 0..2047
        int k   = idx >> 5;              // 0..63
        int n4  = (idx & 31) * 4;        // 0..124
        const float* p = Ew + (size_t)k * 256 + jb * 128 + n4;
        float4 v = make_float4(p[0], p[1], p[2], p[3]);
        unsigned int byte = (unsigned)k * 256 + (((unsigned)n4 * 2) ^ (((unsigned)k & 7) << 4));
        unsigned int i8 = (jb * 16384 + byte) >> 3;
        g_Bh[i8] = pack4_hi(v);
        g_Bl[i8] = pack4_hi(resid4(v));
    }
}

// ---------------- K1: QKV node GEMM (fp32) ----------------------------------
__global__ __launch_bounds__(128) void qkv_kernel(
    const float* __restrict__ x,
    const float* __restrict__ Qw, const float* __restrict__ Qb,
    const float* __restrict__ Kw, const float* __restrict__ Kb,
    const float* __restrict__ Vw, const float* __restrict__ Vb)
{
    __shared__ float As[64][64];
    __shared__ float Bs[64][128];
    const int t   = threadIdx.x;
    const int m0  = blockIdx.x * 64;
    const int sel = blockIdx.y;
    const float* W  = (sel == 0) ? Qw : ((sel == 1) ? Kw : Vw);
    const float* Bv = (sel == 0) ? Qb : ((sel == 1) ? Kb : Vb);
    float* out      = (sel == 0) ? g_Q : ((sel == 1) ? g_K : g_V);

    #pragma unroll
    for (int l = 0; l < 8; l++) {
        int idx = l * 128 + t;
        int m  = idx >> 4;
        int k4 = (idx & 15) * 4;
        float4 v = make_float4(0.f, 0.f, 0.f, 0.f);
        if (m0 + m < NNODES) v = *(const float4*)(x + (size_t)(m0 + m) * 64 + k4);
        As[k4 + 0][m ^ (((k4 + 0) & 7) << 3)] = v.x;
        As[k4 + 1][m ^ (((k4 + 1) & 7) << 3)] = v.y;
        As[k4 + 2][m ^ (((k4 + 2) & 7) << 3)] = v.z;
        As[k4 + 3][m ^ (((k4 + 3) & 7) << 3)] = v.w;
    }
    #pragma unroll
    for (int l = 0; l < 16; l++) {
        int idx = l * 128 + t;
        int k  = idx >> 5;
        int n4 = (idx & 31) * 4;
        *(float4*)&Bs[k][n4] = *(const float4*)(W + (size_t)k * HD + n4);
    }
    __syncthreads();

    const int tx = t & 15, ty = t >> 4;
    float acc[8][8];
    #pragma unroll
    for (int i = 0; i < 8; i++)
        #pragma unroll
        for (int j = 0; j < 8; j++) acc[i][j] = 0.f;

    #pragma unroll 4
    for (int k = 0; k < 64; k++) {
        int ar = ((ty ^ (k & 7)) << 3);
        float4 a0 = *(const float4*)&As[k][ar];
        float4 a1 = *(const float4*)&As[k][ar + 4];
        float4 b0 = *(const float4*)&Bs[k][tx * 8];
        float4 b1 = *(const float4*)&Bs[k][tx * 8 + 4];
        float av[8] = {a0.x, a0.y, a0.z, a0.w, a1.x, a1.y, a1.z, a1.w};
        #pragma unroll
        for (int i = 0; i < 8; i++) {
            acc[i][0] += av[i] * b0.x; acc[i][1] += av[i] * b0.y;
            acc[i][2] += av[i] * b0.z; acc[i][3] += av[i] * b0.w;
            acc[i][4] += av[i] * b1.x; acc[i][5] += av[i] * b1.y;
            acc[i][6] += av[i] * b1.z; acc[i][7] += av[i] * b1.w;
        }
    }

    float4 bias0 = *(const float4*)(Bv + tx * 8);
    float4 bias1 = *(const float4*)(Bv + tx * 8 + 4);
    #pragma unroll
    for (int i = 0; i < 8; i++) {
        int gm = m0 + ty * 8 + i;
        if (gm < NNODES) {
            float4 o0 = make_float4(acc[i][0] + bias0.x, acc[i][1] + bias0.y,
                                    acc[i][2] + bias0.z, acc[i][3] + bias0.w);
            float4 o1 = make_float4(acc[i][4] + bias1.x, acc[i][5] + bias1.y,
                                    acc[i][6] + bias1.z, acc[i][7] + bias1.w);
            *(float4*)(out + (size_t)gm * HD + tx * 8)     = o0;
            *(float4*)(out + (size_t)gm * HD + tx * 8 + 4) = o1;
        }
    }
}

// ---------------- K2: edge GEMM via mma.sync bf16 hi/lo + epilogue ----------
// BM=128 edges, BN=128 cols (4 heads), K=64. 256 threads / 8 warps.
#define SM_A_HI 0
#define SM_A_LO 16384
#define SM_B_HI 32768
#define SM_B_LO 49152
#define ES_STRIDE 132
#define SMEM_EDGE_TOTAL (128 * ES_STRIDE * 4)   // 67584 >= 65536 tile bytes

__global__ __launch_bounds__(256) void edge_kernel(
    const float* __restrict__ eattr, const int* __restrict__ eidx,
    const float* __restrict__ Eb, const float* __restrict__ Aw,
    float* __restrict__ outbuf)
{
    extern __shared__ char smem[];
    float* Es = (float*)smem;
    const uint32_t sbase = smem_u32(smem);
    const int t   = threadIdx.x;
    const int l   = t & 31;
    const int w   = t >> 5;
    const int m0  = blockIdx.x * 128;
    const int jb  = blockIdx.y;

    // ---- A tile: 128 edges x 64 K -> hi/lo bf16, swizzled (128B rows)
    #pragma unroll
    for (int it = 0; it < 8; it++) {
        int idx = it * 256 + t;
        int row = idx >> 4;
        int c4  = (idx & 15) * 4;
        float4 v = *(const float4*)(eattr + (size_t)(m0 + row) * 64 + c4);
        unsigned int byte = (unsigned)row * 128 + (((unsigned)c4 * 2) ^ (((unsigned)row & 7) << 4));
        *(unsigned long long*)(smem + SM_A_HI + byte) = pack4_hi(v);
        *(unsigned long long*)(smem + SM_A_LO + byte) = pack4_hi(resid4(v));
    }
    // ---- B tiles: linear copy of pre-swizzled images (16KB each)
    {
        const ulonglong2* bh = (const ulonglong2*)(g_Bh + jb * 2048);
        const ulonglong2* bl = (const ulonglong2*)(g_Bl + jb * 2048);
        ulonglong2* dh = (ulonglong2*)(smem + SM_B_HI);
        ulonglong2* dl = (ulonglong2*)(smem + SM_B_LO);
        #pragma unroll
        for (int it = 0; it < 4; it++) {
            int idx = it * 256 + t;
            dh[idx] = bh[idx];
            dl[idx] = bl[idx];
        }
    }
    __syncthreads();

    // ---- MMA: warp w owns rows 16w..16w+15, all 128 cols
    float acc[16][4];
    #pragma unroll
    for (int j = 0; j < 16; j++)
        #pragma unroll
        for (int q = 0; q < 4; q++) acc[j][q] = 0.f;

    const int m0w  = w * 16;
    const int arow = m0w + (l & 15);
    const int asw  = ((l & 15) & 7) << 4;
    const int lx   = l & 7;
    const int bl15 = l & 15;

    const uint32_t Abase[2] = {sbase + SM_A_HI, sbase + SM_A_LO};
    const uint32_t Bbase[2] = {sbase + SM_B_HI, sbase + SM_B_LO};
    const int pA[3] = {0, 0, 1};
    const int pB[3] = {0, 1, 0};

    #pragma unroll
    for (int p = 0; p < 3; p++) {
        uint32_t Ab = Abase[pA[p]];
        uint32_t Bb = Bbase[pB[p]];
        #pragma unroll
        for (int ks = 0; ks < 4; ks++) {
            uint32_t a[4];
            uint32_t aaddr = Ab + (unsigned)arow * 128 +
                             (((unsigned)(32 * ks + (l & 16))) ^ (unsigned)asw);
            ldmatrix_x4(a, aaddr);
            uint32_t brow = Bb + (unsigned)(16 * ks + bl15) * 256;
            #pragma unroll
            for (int j = 0; j < 16; j++) {
                uint32_t b[2];
                ldmatrix_x2t(b, brow + (((unsigned)(j ^ lx)) << 4));
                mma16816(acc[j], a, b);
            }
        }
    }
    __syncthreads();    // all warps done reading A/B; overlay Es

    // ---- write D fragments into Es[128][132]
    {
        const int g  = l >> 2;
        const int t2 = (l & 3) * 2;
        #pragma unroll
        for (int j = 0; j < 16; j++) {
            int col = j * 8 + t2;
            *(float2*)&Es[(m0w + g) * ES_STRIDE + col]     = make_float2(acc[j][0], acc[j][1]);
            *(float2*)&Es[(m0w + g + 8) * ES_STRIDE + col] = make_float2(acc[j][2], acc[j][3]);
        }
    }
    __syncthreads();

    // ---- epilogue: 2 threads per edge, 2 heads each
    const int el = t >> 1;
    const int e  = m0 + el;
    const int hp = (t & 1) * 2;
    const int src = eidx[e];
    const int dst = eidx[NEDGES + e];
    const float* Krow = g_K + (size_t)src * HD;
    const float* Qrow = g_Q + (size_t)dst * HD;
    float* oEp = outbuf + (size_t)OUT_OE + (size_t)e * HD;
    const float* EsRow = Es + el * ES_STRIDE;

    #pragma unroll
    for (int u = 0; u < 2; u++) {
        int hloc = hp + u;           // 0..3
        int h    = jb * 4 + hloc;    // global head
        int colK = h * 16;           // col in K/Q/oE

        float sc[16];
        float a = 0.f;
        #pragma unroll
        for (int d4 = 0; d4 < 4; d4++) {
            float4 s1v = *(const float4*)(EsRow + hloc * 32 + d4 * 4);
            float4 s2v = *(const float4*)(EsRow + hloc * 32 + 16 + d4 * 4);
            float4 kv  = *(const float4*)(Krow + colK + d4 * 4);
            float4 qv  = *(const float4*)(Qrow + colK + d4 * 4);
            float s1a[4] = {s1v.x, s1v.y, s1v.z, s1v.w};
            float s2a[4] = {s2v.x, s2v.y, s2v.z, s2v.w};
            float kqa[4] = {kv.x + qv.x, kv.y + qv.y, kv.z + qv.z, kv.w + qv.w};
            #pragma unroll
            for (int q = 0; q < 4; q++) {
                int d = d4 * 4 + q;
                float s1 = s1a[q] + __ldg(Eb + h * 32 + d);
                float s2 = s2a[q] + __ldg(Eb + h * 32 + 16 + d);
                float pr = s1 * s2;
                float r  = sqrtf(fabsf(pr));
                sc[d] = copysignf(r, pr) + kqa[q];
                a += sc[d] * __ldg(Aw + d * 8 + h);
            }
        }
        *(float4*)(oEp + colK)      = *(float4*)&sc[0];
        *(float4*)(oEp + colK + 4)  = *(float4*)&sc[4];
        *(float4*)(oEp + colK + 8)  = *(float4*)&sc[8];
        *(float4*)(oEp + colK + 12) = *(float4*)&sc[12];

        a = fminf(fmaxf(a, -5.0f), 5.0f);
        g_w[(size_t)e * 8 + h] = expf(a);
    }
}

// ---------------- K3: CSR build ---------------------------------------------
__global__ void zero_kernel()
{
    int i = blockIdx.x * blockDim.x + threadIdx.x;
    if (i < NNODES) g_deg[i] = 0;
}
__global__ void hist_kernel(const int* __restrict__ eidx)
{
    int e = blockIdx.x * blockDim.x + threadIdx.x;
    if (e < NEDGES) atomicAdd(&g_deg[eidx[NEDGES + e]], 1);
}
__global__ void scan_kernel()
{
    __shared__ int s[1024];
    __shared__ int carry_s;
    const int t = threadIdx.x;
    if (t == 0) carry_s = 0;
    __syncthreads();
    for (int base = 0; base < NNODES; base += 1024) {
        int idx = base + t;
        int v = (idx < NNODES) ? g_deg[idx] : 0;
        s[t] = v;
        __syncthreads();
        for (int off = 1; off < 1024; off <<= 1) {
            int xv = 0;
            if (t >= off) xv = s[t - off];
            __syncthreads();
            s[t] += xv;
            __syncthreads();
        }
        int excl = s[t] - v + carry_s;
        if (idx < NNODES) { g_off[idx] = excl; g_cursor[idx] = excl; }
        __syncthreads();
        if (t == 0) carry_s += s[1023];
        __syncthreads();
    }
    if (t == 0) g_off[NNODES] = carry_s;
}
__global__ void scatter_kernel(const int* __restrict__ eidx)
{
    int e = blockIdx.x * blockDim.x + threadIdx.x;
    if (e < NEDGES) {
        int dst = eidx[NEDGES + e];
        int p = atomicAdd(&g_cursor[dst], 1);
        g_csr[p] = make_int2(e, eidx[e]);
    }
}

// ---------------- K4: fused softmax + aggregation ---------------------------
__global__ __launch_bounds__(128) void node_kernel(
    const float* __restrict__ VeRow,
    const float* __restrict__ oE,
    float* __restrict__ n_out)
{
    __shared__ int2  stage[128];
    __shared__ float rowS[8][17];
    const int n = blockIdx.x;
    const int t = threadIdx.x;
    const int h = t >> 4, c = t & 15;
    const int beg = g_off[n], end = g_off[n + 1];

    float den = 0.f, accV = 0.f, accR = 0.f;
    for (int base = beg; base < end; base += 128) {
        int cnt = min(128, end - base);
        __syncthreads();
        if (t < cnt) stage[t] = g_csr[base + t];
        __syncthreads();
        #pragma unroll 4
        for (int i = 0; i < cnt; i++) {
            int e   = stage[i].x;
            int src = stage[i].y;
            float wv = g_w[(size_t)e * 8 + h];
            den  += wv;
            accV += wv * g_V[(size_t)src * HD + t];
            accR += wv * oE[(size_t)e * HD + t];
        }
    }
    float inv = 1.f / (den + 1e-16f);

    rowS[h][c] = accR * inv;
    __syncthreads();
    float r = 0.f;
    #pragma unroll
    for (int d = 0; d < 16; d++)
        r += rowS[h][d] * VeRow[d * HD + h * 16 + c];

    n_out[(size_t)n * HD + t] = accV * inv + r;
}

// ---------------- launch -----------------------------------------------------
extern "C" void kernel_launch(void* const* d_in, const int* in_sizes, int n_in,
                              void* d_out, int out_size)
{
    const float* x     = (const float*)d_in[0];
    const float* eattr = (const float*)d_in[1];
    const int*   eidx  = (const int*)  d_in[2];
    const float* Qw = (const float*)d_in[3];  const float* Qb = (const float*)d_in[4];
    const float* Kw = (const float*)d_in[5];  const float* Kb = (const float*)d_in[6];
    const float* Ew = (const float*)d_in[7];  const float* Eb = (const float*)d_in[8];
    const float* Vw = (const float*)d_in[9];  const float* Vb = (const float*)d_in[10];
    const float* Aw = (const float*)d_in[11]; const float* VeRow = (const float*)d_in[12];
    float* out = (float*)d_out;

    cudaFuncSetAttribute(edge_kernel, cudaFuncAttributeMaxDynamicSharedMemorySize,
                         SMEM_EDGE_TOTAL);

    bprep_kernel<<<2, 256>>>(Ew);
    zero_kernel<<<(NNODES + 255) / 256, 256>>>();
    qkv_kernel<<<dim3((NNODES + 63) / 64, 3), 128>>>(x, Qw, Qb, Kw, Kb, Vw, Vb);
    hist_kernel<<<(NEDGES + 255) / 256, 256>>>(eidx);
    scan_kernel<<<1, 1024>>>();
    edge_kernel<<<dim3(NEDGES / 128, 2), 256, SMEM_EDGE_TOTAL>>>(eattr, eidx, Eb, Aw, out);
    scatter_kernel<<<(NEDGES + 255) / 256, 256>>>(eidx);
    node_kernel<<<NNODES, 128>>>(VeRow, out + OUT_OE, out);
}

// round 5
// speedup vs baseline: 1.5984x; 1.0895x over previous
#include <cuda_runtime.h>
#include <cuda_bf16.h>
#include <math.h>
#include <stdint.h>

#define NNODES 20000
#define NEDGES 320000
#define HD 128
#define OUT_OE (NNODES * HD)

// ---------------- scratch ----------------------------------------------------
__device__ float g_Q[NNODES * HD];
__device__ float g_K[NNODES * HD];
__device__ float g_V[NNODES * HD];
__device__ float g_w[NEDGES * 8];
__device__ int   g_deg[NNODES];
__device__ int   g_off[NNODES + 1];
__device__ int   g_cursor[NNODES];
__device__ int2  g_csr[NEDGES];
#define SCAN_BLK 256
#define NSCB ((NNODES + SCAN_BLK - 1) / SCAN_BLK)
__device__ int   g_bsum[NSCB];
__device__ int   g_bpre[NSCB];
// pre-swizzled bf16 B images: [2 halves][64 k][128 n], 16KB per half per img
__device__ unsigned long long g_Bh[4096];
__device__ unsigned long long g_Bl[4096];

// ---------------- helpers ----------------------------------------------------
__device__ __forceinline__ uint32_t smem_u32(const void* p) {
    uint32_t a;
    asm("{ .reg .u64 t; cvta.to.shared.u64 t, %1; cvt.u32.u64 %0, t; }" : "=r"(a) : "l"(p));
    return a;
}
__device__ __forceinline__ unsigned long long pack4_hi(float4 v) {
    unsigned short h0 = __bfloat16_as_ushort(__float2bfloat16(v.x));
    unsigned short h1 = __bfloat16_as_ushort(__float2bfloat16(v.y));
    unsigned short h2 = __bfloat16_as_ushort(__float2bfloat16(v.z));
    unsigned short h3 = __bfloat16_as_ushort(__float2bfloat16(v.w));
    return (unsigned long long)h0 | ((unsigned long long)h1 << 16) |
           ((unsigned long long)h2 << 32) | ((unsigned long long)h3 << 48);
}
__device__ __forceinline__ float4 resid4(float4 v) {
    return make_float4(
        v.x - __bfloat162float(__float2bfloat16(v.x)),
        v.y - __bfloat162float(__float2bfloat16(v.y)),
        v.z - __bfloat162float(__float2bfloat16(v.z)),
        v.w - __bfloat162float(__float2bfloat16(v.w)));
}
__device__ __forceinline__ void ldmatrix_x4(uint32_t* r, uint32_t addr) {
    asm volatile("ldmatrix.sync.aligned.m8n8.x4.shared.b16 {%0,%1,%2,%3}, [%4];"
                 : "=r"(r[0]), "=r"(r[1]), "=r"(r[2]), "=r"(r[3]) : "r"(addr));
}
__device__ __forceinline__ void ldmatrix_x4t(uint32_t* r, uint32_t addr) {
    asm volatile("ldmatrix.sync.aligned.m8n8.x4.trans.shared.b16 {%0,%1,%2,%3}, [%4];"
                 : "=r"(r[0]), "=r"(r[1]), "=r"(r[2]), "=r"(r[3]) : "r"(addr));
}
__device__ __forceinline__ void mma16816(float* c, const uint32_t* a, const uint32_t* b) {
    asm volatile(
        "mma.sync.aligned.m16n8k16.row.col.f32.bf16.bf16.f32 "
        "{%0,%1,%2,%3}, {%4,%5,%6,%7}, {%8,%9}, {%0,%1,%2,%3};"
        : "+f"(c[0]), "+f"(c[1]), "+f"(c[2]), "+f"(c[3])
        : "r"(a[0]), "r"(a[1]), "r"(a[2]), "r"(a[3]), "r"(b[0]), "r"(b[1]));
}

// ---------------- K0: precompute bf16 hi/lo images of Ew --------------------
__global__ void bprep_kernel(const float* __restrict__ Ew)
{
    const int jb = blockIdx.x;
    const int t  = threadIdx.x;   // 256
    for (int it = 0; it < 8; it++) {
        int idx = it * 256 + t;          // 0..2047
        int k   = idx >> 5;              // 0..63
        int n4  = (idx & 31) * 4;        // 0..124
        const float* p = Ew + (size_t)k * 256 + jb * 128 + n4;
        float4 v = make_float4(p[0], p[1], p[2], p[3]);
        unsigned int byte = (unsigned)k * 256 + (((unsigned)n4 * 2) ^ (((unsigned)k & 7) << 4));
        unsigned int i8 = (jb * 16384 + byte) >> 3;
        g_Bh[i8] = pack4_hi(v);
        g_Bl[i8] = pack4_hi(resid4(v));
    }
}

// ---------------- K1: QKV node GEMM (fp32) ----------------------------------
__global__ __launch_bounds__(128) void qkv_kernel(
    const float* __restrict__ x,
    const float* __restrict__ Qw, const float* __restrict__ Qb,
    const float* __restrict__ Kw, const float* __restrict__ Kb,
    const float* __restrict__ Vw, const float* __restrict__ Vb)
{
    __shared__ float As[64][64];
    __shared__ float Bs[64][128];
    const int t   = threadIdx.x;
    const int m0  = blockIdx.x * 64;
    const int sel = blockIdx.y;
    const float* W  = (sel == 0) ? Qw : ((sel == 1) ? Kw : Vw);
    const float* Bv = (sel == 0) ? Qb : ((sel == 1) ? Kb : Vb);
    float* out      = (sel == 0) ? g_Q : ((sel == 1) ? g_K : g_V);

    #pragma unroll
    for (int l = 0; l < 8; l++) {
        int idx = l * 128 + t;
        int m  = idx >> 4;
        int k4 = (idx & 15) * 4;
        float4 v = make_float4(0.f, 0.f, 0.f, 0.f);
        if (m0 + m < NNODES) v = *(const float4*)(x + (size_t)(m0 + m) * 64 + k4);
        As[k4 + 0][m ^ (((k4 + 0) & 7) << 3)] = v.x;
        As[k4 + 1][m ^ (((k4 + 1) & 7) << 3)] = v.y;
        As[k4 + 2][m ^ (((k4 + 2) & 7) << 3)] = v.z;
        As[k4 + 3][m ^ (((k4 + 3) & 7) << 3)] = v.w;
    }
    #pragma unroll
    for (int l = 0; l < 16; l++) {
        int idx = l * 128 + t;
        int k  = idx >> 5;
        int n4 = (idx & 31) * 4;
        *(float4*)&Bs[k][n4] = *(const float4*)(W + (size_t)k * HD + n4);
    }
    __syncthreads();

    const int tx = t & 15, ty = t >> 4;
    float acc[8][8];
    #pragma unroll
    for (int i = 0; i < 8; i++)
        #pragma unroll
        for (int j = 0; j < 8; j++) acc[i][j] = 0.f;

    #pragma unroll 4
    for (int k = 0; k < 64; k++) {
        int ar = ((ty ^ (k & 7)) << 3);
        float4 a0 = *(const float4*)&As[k][ar];
        float4 a1 = *(const float4*)&As[k][ar + 4];
        float4 b0 = *(const float4*)&Bs[k][tx * 8];
        float4 b1 = *(const float4*)&Bs[k][tx * 8 + 4];
        float av[8] = {a0.x, a0.y, a0.z, a0.w, a1.x, a1.y, a1.z, a1.w};
        #pragma unroll
        for (int i = 0; i < 8; i++) {
            acc[i][0] += av[i] * b0.x; acc[i][1] += av[i] * b0.y;
            acc[i][2] += av[i] * b0.z; acc[i][3] += av[i] * b0.w;
            acc[i][4] += av[i] * b1.x; acc[i][5] += av[i] * b1.y;
            acc[i][6] += av[i] * b1.z; acc[i][7] += av[i] * b1.w;
        }
    }

    float4 bias0 = *(const float4*)(Bv + tx * 8);
    float4 bias1 = *(const float4*)(Bv + tx * 8 + 4);
    #pragma unroll
    for (int i = 0; i < 8; i++) {
        int gm = m0 + ty * 8 + i;
        if (gm < NNODES) {
            float4 o0 = make_float4(acc[i][0] + bias0.x, acc[i][1] + bias0.y,
                                    acc[i][2] + bias0.z, acc[i][3] + bias0.w);
            float4 o1 = make_float4(acc[i][4] + bias1.x, acc[i][5] + bias1.y,
                                    acc[i][6] + bias1.z, acc[i][7] + bias1.w);
            *(float4*)(out + (size_t)gm * HD + tx * 8)     = o0;
            *(float4*)(out + (size_t)gm * HD + tx * 8 + 4) = o1;
        }
    }
}

// ---------------- K2: edge GEMM via mma.sync bf16 hi/lo + epilogue ----------
// BM=128 edges, BN=128 cols (4 heads), K=64. 256 threads / 8 warps.
#define SM_A_HI 0
#define SM_A_LO 16384
#define SM_B_HI 32768
#define SM_B_LO 49152
#define ES_STRIDE 132
#define SMEM_EDGE_TOTAL (128 * ES_STRIDE * 4)   // 67584 >= 65536 tile bytes

__global__ __launch_bounds__(256) void edge_kernel(
    const float* __restrict__ eattr, const int* __restrict__ eidx,
    const float* __restrict__ Eb, const float* __restrict__ Aw,
    float* __restrict__ outbuf)
{
    extern __shared__ char smem[];
    float* Es = (float*)smem;
    const uint32_t sbase = smem_u32(smem);
    const int t   = threadIdx.x;
    const int l   = t & 31;
    const int w   = t >> 5;
    const int m0  = blockIdx.x * 128;
    const int jb  = blockIdx.y;

    // ---- A tile: 128 edges x 64 K -> hi/lo bf16, swizzled (128B rows)
    #pragma unroll
    for (int it = 0; it < 8; it++) {
        int idx = it * 256 + t;
        int row = idx >> 4;
        int c4  = (idx & 15) * 4;
        const float4* ap = (const float4*)(eattr + (size_t)(m0 + row) * 64 + c4);
        float4 v = __ldcs(ap);
        unsigned int byte = (unsigned)row * 128 + (((unsigned)c4 * 2) ^ (((unsigned)row & 7) << 4));
        *(unsigned long long*)(smem + SM_A_HI + byte) = pack4_hi(v);
        *(unsigned long long*)(smem + SM_A_LO + byte) = pack4_hi(resid4(v));
    }
    // ---- B tiles: linear copy of pre-swizzled images (16KB each)
    {
        const ulonglong2* bh = (const ulonglong2*)(g_Bh + jb * 2048);
        const ulonglong2* bl = (const ulonglong2*)(g_Bl + jb * 2048);
        ulonglong2* dh = (ulonglong2*)(smem + SM_B_HI);
        ulonglong2* dl = (ulonglong2*)(smem + SM_B_LO);
        #pragma unroll
        for (int it = 0; it < 4; it++) {
            int idx = it * 256 + t;
            dh[idx] = bh[idx];
            dl[idx] = bl[idx];
        }
    }
    __syncthreads();

    // ---- MMA: warp w owns rows 16w..16w+15, all 128 cols
    float acc[16][4];
    #pragma unroll
    for (int j = 0; j < 16; j++)
        #pragma unroll
        for (int q = 0; q < 4; q++) acc[j][q] = 0.f;

    const int m0w  = w * 16;
    const int arow = m0w + (l & 15);
    const int asw  = ((l & 15) & 7) << 4;
    const int lx   = l & 7;
    const int bl15 = l & 15;
    const int jhi  = l >> 4;         // lanes 16-31 fetch the second fragment

    #pragma unroll
    for (int ks = 0; ks < 4; ks++) {
        uint32_t ah[4], al[4];
        uint32_t aoff = (unsigned)arow * 128 +
                        (((unsigned)(32 * ks + (l & 16))) ^ (unsigned)asw);
        ldmatrix_x4(ah, sbase + SM_A_HI + aoff);
        ldmatrix_x4(al, sbase + SM_A_LO + aoff);
        uint32_t brow_h = sbase + SM_B_HI + (unsigned)(16 * ks + bl15) * 256;
        uint32_t brow_l = sbase + SM_B_LO + (unsigned)(16 * ks + bl15) * 256;
        #pragma unroll
        for (int j = 0; j < 16; j += 2) {
            uint32_t boff = ((unsigned)((j + jhi) ^ lx)) << 4;
            uint32_t bh[4], blo[4];
            ldmatrix_x4t(bh,  brow_h + boff);
            ldmatrix_x4t(blo, brow_l + boff);
            mma16816(acc[j],     ah, bh);
            mma16816(acc[j + 1], ah, bh + 2);
            mma16816(acc[j],     al, bh);
            mma16816(acc[j + 1], al, bh + 2);
            mma16816(acc[j],     ah, blo);
            mma16816(acc[j + 1], ah, blo + 2);
        }
    }
    __syncthreads();    // all warps done reading A/B; overlay Es

    // ---- write D fragments into Es[128][132]
    {
        const int g  = l >> 2;
        const int t2 = (l & 3) * 2;
        #pragma unroll
        for (int j = 0; j < 16; j++) {
            int col = j * 8 + t2;
            *(float2*)&Es[(m0w + g) * ES_STRIDE + col]     = make_float2(acc[j][0], acc[j][1]);
            *(float2*)&Es[(m0w + g + 8) * ES_STRIDE + col] = make_float2(acc[j][2], acc[j][3]);
        }
    }
    __syncthreads();

    // ---- epilogue: 2 threads per edge, 2 heads each
    const int el = t >> 1;
    const int e  = m0 + el;
    const int hp = (t & 1) * 2;
    const int src = eidx[e];
    const int dst = eidx[NEDGES + e];
    const float* Krow = g_K + (size_t)src * HD;
    const float* Qrow = g_Q + (size_t)dst * HD;
    float* oEp = outbuf + (size_t)OUT_OE + (size_t)e * HD;
    const float* EsRow = Es + el * ES_STRIDE;

    #pragma unroll
    for (int u = 0; u < 2; u++) {
        int hloc = hp + u;           // 0..3
        int h    = jb * 4 + hloc;    // global head
        int colK = h * 16;           // col in K/Q/oE

        float sc[16];
        float a = 0.f;
        #pragma unroll
        for (int d4 = 0; d4 < 4; d4++) {
            float4 s1v = *(const float4*)(EsRow + hloc * 32 + d4 * 4);
            float4 s2v = *(const float4*)(EsRow + hloc * 32 + 16 + d4 * 4);
            float4 kv  = *(const float4*)(Krow + colK + d4 * 4);
            float4 qv  = *(const float4*)(Qrow + colK + d4 * 4);
            float s1a[4] = {s1v.x, s1v.y, s1v.z, s1v.w};
            float s2a[4] = {s2v.x, s2v.y, s2v.z, s2v.w};
            float kqa[4] = {kv.x + qv.x, kv.y + qv.y, kv.z + qv.z, kv.w + qv.w};
            #pragma unroll
            for (int q = 0; q < 4; q++) {
                int d = d4 * 4 + q;
                float s1 = s1a[q] + __ldg(Eb + h * 32 + d);
                float s2 = s2a[q] + __ldg(Eb + h * 32 + 16 + d);
                float pr = s1 * s2;
                float r  = sqrtf(fabsf(pr));
                sc[d] = copysignf(r, pr) + kqa[q];
                a += sc[d] * __ldg(Aw + d * 8 + h);
            }
        }
        __stcs((float4*)(oEp + colK),      *(float4*)&sc[0]);
        __stcs((float4*)(oEp + colK + 4),  *(float4*)&sc[4]);
        __stcs((float4*)(oEp + colK + 8),  *(float4*)&sc[8]);
        __stcs((float4*)(oEp + colK + 12), *(float4*)&sc[12]);

        a = fminf(fmaxf(a, -5.0f), 5.0f);
        g_w[(size_t)e * 8 + h] = expf(a);
    }
}

// ---------------- K3: CSR build ---------------------------------------------
__global__ void zero_kernel()
{
    int i = blockIdx.x * blockDim.x + threadIdx.x;
    if (i < NNODES) g_deg[i] = 0;
}
__global__ void hist_kernel(const int* __restrict__ eidx)
{
    int e = blockIdx.x * blockDim.x + threadIdx.x;
    if (e < NEDGES) atomicAdd(&g_deg[eidx[NEDGES + e]], 1);
}
// hierarchical scan: S1 block-local, S2 block sums, S3 add + cursor
__global__ __launch_bounds__(SCAN_BLK) void scan1_kernel()
{
    __shared__ int warpsum[SCAN_BLK / 32];
    const int b = blockIdx.x, t = threadIdx.x;
    const int i = b * SCAN_BLK + t;
    int v = (i < NNODES) ? g_deg[i] : 0;
    int s = v;
    #pragma unroll
    for (int o = 1; o < 32; o <<= 1) {
        int u = __shfl_up_sync(0xffffffffu, s, o);
        if ((t & 31) >= o) s += u;
    }
    if ((t & 31) == 31) warpsum[t >> 5] = s;
    __syncthreads();
    if (t < SCAN_BLK / 32) {
        int ws = warpsum[t];
        #pragma unroll
        for (int o = 1; o < SCAN_BLK / 32; o <<= 1) {
            int u = __shfl_up_sync((1u << (SCAN_BLK / 32)) - 1u, ws, o);
            if (t >= o) ws += u;
        }
        warpsum[t] = ws;
    }
    __syncthreads();
    int excl = s - v + ((t >> 5) ? warpsum[(t >> 5) - 1] : 0);
    if (i < NNODES) g_off[i] = excl;
    if (t == SCAN_BLK - 1) g_bsum[b] = excl + v;
}
__global__ void scan2_kernel()
{
    __shared__ int ws[4];
    const int t = threadIdx.x;   // 128
    int v = (t < NSCB) ? g_bsum[t] : 0;
    int s = v;
    #pragma unroll
    for (int o = 1; o < 32; o <<= 1) {
        int u = __shfl_up_sync(0xffffffffu, s, o);
        if ((t & 31) >= o) s += u;
    }
    if ((t & 31) == 31) ws[t >> 5] = s;
    __syncthreads();
    if (t < 4) {
        int wv = ws[t];
        #pragma unroll
        for (int o = 1; o < 4; o <<= 1) {
            int u = __shfl_up_sync(0xfu, wv, o);
            if (t >= o) wv += u;
        }
        ws[t] = wv;
    }
    __syncthreads();
    int excl = s - v + ((t >> 5) ? ws[(t >> 5) - 1] : 0);
    if (t < NSCB) g_bpre[t] = excl;
    if (t == NSCB - 1) g_off[NNODES] = excl + v;
}
__global__ void scan3_kernel()
{
    int i = blockIdx.x * blockDim.x + threadIdx.x;
    if (i < NNODES) {
        int o = g_off[i] + g_bpre[i >> 8];
        g_off[i] = o;
        g_cursor[i] = o;
    }
}
__global__ void scatter_kernel(const int* __restrict__ eidx)
{
    int e = blockIdx.x * blockDim.x + threadIdx.x;
    if (e < NEDGES) {
        int dst = eidx[NEDGES + e];
        int p = atomicAdd(&g_cursor[dst], 1);
        g_csr[p] = make_int2(e, eidx[e]);
    }
}

// ---------------- K4: fused softmax + aggregation ---------------------------
__global__ __launch_bounds__(128) void node_kernel(
    const float* __restrict__ VeRow,
    const float* __restrict__ oE,
    float* __restrict__ n_out)
{
    __shared__ int2  stage[128];
    __shared__ float rowS[8][17];
    const int n = blockIdx.x;
    const int t = threadIdx.x;
    const int h = t >> 4, c = t & 15;
    const int beg = g_off[n], end = g_off[n + 1];

    float den = 0.f, accV = 0.f, accR = 0.f;
    for (int base = beg; base < end; base += 128) {
        int cnt = min(128, end - base);
        __syncthreads();
        if (t < cnt) stage[t] = g_csr[base + t];
        __syncthreads();
        #pragma unroll 4
        for (int i = 0; i < cnt; i++) {
            int e   = stage[i].x;
            int src = stage[i].y;
            float wv = g_w[(size_t)e * 8 + h];
            den  += wv;
            accV += wv * g_V[(size_t)src * HD + t];
            accR += wv * __ldcs(oE + (size_t)e * HD + t);
        }
    }
    float inv = 1.f / (den + 1e-16f);

    rowS[h][c] = accR * inv;
    __syncthreads();
    float r = 0.f;
    #pragma unroll
    for (int d = 0; d < 16; d++)
        r += rowS[h][d] * VeRow[d * HD + h * 16 + c];

    n_out[(size_t)n * HD + t] = accV * inv + r;
}

// ---------------- launch -----------------------------------------------------
extern "C" void kernel_launch(void* const* d_in, const int* in_sizes, int n_in,
                              void* d_out, int out_size)
{
    const float* x     = (const float*)d_in[0];
    const float* eattr = (const float*)d_in[1];
    const int*   eidx  = (const int*)  d_in[2];
    const float* Qw = (const float*)d_in[3];  const float* Qb = (const float*)d_in[4];
    const float* Kw = (const float*)d_in[5];  const float* Kb = (const float*)d_in[6];
    const float* Ew = (const float*)d_in[7];  const float* Eb = (const float*)d_in[8];
    const float* Vw = (const float*)d_in[9];  const float* Vb = (const float*)d_in[10];
    const float* Aw = (const float*)d_in[11]; const float* VeRow = (const float*)d_in[12];
    float* out = (float*)d_out;

    cudaFuncSetAttribute(edge_kernel, cudaFuncAttributeMaxDynamicSharedMemorySize,
                         SMEM_EDGE_TOTAL);

    bprep_kernel<<<2, 256>>>(Ew);                                           // 1
    zero_kernel<<<(NNODES + 255) / 256, 256>>>();                           // 2
    qkv_kernel<<<dim3((NNODES + 63) / 64, 3), 128>>>(x, Qw, Qb, Kw, Kb, Vw, Vb); // 3
    edge_kernel<<<dim3(NEDGES / 128, 2), 256, SMEM_EDGE_TOTAL>>>(eattr, eidx, Eb, Aw, out); // 4 (profiled)
    hist_kernel<<<(NEDGES + 255) / 256, 256>>>(eidx);                       // 5
    scan1_kernel<<<NSCB, SCAN_BLK>>>();                                     // 6
    scan2_kernel<<<1, 128>>>();                                             // 7
    scan3_kernel<<<(NNODES + 255) / 256, 256>>>();                          // 8
    scatter_kernel<<<(NEDGES + 255) / 256, 256>>>(eidx);                    // 9
    node_kernel<<<NNODES, 128>>>(VeRow, out + OUT_OE, out);                 // 10
}

// round 6
// speedup vs baseline: 1.8391x; 1.1505x over previous
#include <cuda_runtime.h>
#include <cuda_bf16.h>
#include <math.h>
#include <stdint.h>

#define NNODES 20000
#define NEDGES 320000
#define HD 128
#define OUT_OE (NNODES * HD)

// ---------------- scratch ----------------------------------------------------
__device__ float g_Q[NNODES * HD];
__device__ float g_K[NNODES * HD];
__device__ float g_V[NNODES * HD];
__device__ float g_w[NEDGES * 8];
__device__ int   g_deg[NNODES];
__device__ int   g_off[NNODES + 1];
__device__ int   g_cursor[NNODES];
__device__ int2  g_csr[NEDGES];
#define SCAN_BLK 256
#define NSCB ((NNODES + SCAN_BLK - 1) / SCAN_BLK)
__device__ int   g_bsum[NSCB];
__device__ int   g_bpre[NSCB];
// pre-swizzled bf16 B images: [2 halves][64 k][128 n], 16KB per half per img
__device__ unsigned long long g_Bh[4096];
__device__ unsigned long long g_Bl[4096];

// ---------------- helpers ----------------------------------------------------
__device__ __forceinline__ uint32_t smem_u32(const void* p) {
    uint32_t a;
    asm("{ .reg .u64 t; cvta.to.shared.u64 t, %1; cvt.u32.u64 %0, t; }" : "=r"(a) : "l"(p));
    return a;
}
__device__ __forceinline__ unsigned long long pack4_hi(float4 v) {
    unsigned short h0 = __bfloat16_as_ushort(__float2bfloat16(v.x));
    unsigned short h1 = __bfloat16_as_ushort(__float2bfloat16(v.y));
    unsigned short h2 = __bfloat16_as_ushort(__float2bfloat16(v.z));
    unsigned short h3 = __bfloat16_as_ushort(__float2bfloat16(v.w));
    return (unsigned long long)h0 | ((unsigned long long)h1 << 16) |
           ((unsigned long long)h2 << 32) | ((unsigned long long)h3 << 48);
}
__device__ __forceinline__ float4 resid4(float4 v) {
    return make_float4(
        v.x - __bfloat162float(__float2bfloat16(v.x)),
        v.y - __bfloat162float(__float2bfloat16(v.y)),
        v.z - __bfloat162float(__float2bfloat16(v.z)),
        v.w - __bfloat162float(__float2bfloat16(v.w)));
}
__device__ __forceinline__ void ldmatrix_x4(uint32_t* r, uint32_t addr) {
    asm volatile("ldmatrix.sync.aligned.m8n8.x4.shared.b16 {%0,%1,%2,%3}, [%4];"
                 : "=r"(r[0]), "=r"(r[1]), "=r"(r[2]), "=r"(r[3]) : "r"(addr));
}
__device__ __forceinline__ void ldmatrix_x4t(uint32_t* r, uint32_t addr) {
    asm volatile("ldmatrix.sync.aligned.m8n8.x4.trans.shared.b16 {%0,%1,%2,%3}, [%4];"
                 : "=r"(r[0]), "=r"(r[1]), "=r"(r[2]), "=r"(r[3]) : "r"(addr));
}
__device__ __forceinline__ void mma16816(float* c, const uint32_t* a, const uint32_t* b) {
    asm volatile(
        "mma.sync.aligned.m16n8k16.row.col.f32.bf16.bf16.f32 "
        "{%0,%1,%2,%3}, {%4,%5,%6,%7}, {%8,%9}, {%0,%1,%2,%3};"
        : "+f"(c[0]), "+f"(c[1]), "+f"(c[2]), "+f"(c[3])
        : "r"(a[0]), "r"(a[1]), "r"(a[2]), "r"(a[3]), "r"(b[0]), "r"(b[1]));
}

// ---------------- K0: precompute bf16 hi/lo images of Ew --------------------
__global__ void bprep_kernel(const float* __restrict__ Ew)
{
    const int jb = blockIdx.x;
    const int t  = threadIdx.x;   // 256
    for (int it = 0; it < 8; it++) {
        int idx = it * 256 + t;          // 0..2047
        int k   = idx >> 5;              // 0..63
        int n4  = (idx & 31) * 4;        // 0..124
        const float* p = Ew + (size_t)k * 256 + jb * 128 + n4;
        float4 v = make_float4(p[0], p[1], p[2], p[3]);
        unsigned int byte = (unsigned)k * 256 + (((unsigned)n4 * 2) ^ (((unsigned)k & 7) << 4));
        unsigned int i8 = (jb * 16384 + byte) >> 3;
        g_Bh[i8] = pack4_hi(v);
        g_Bl[i8] = pack4_hi(resid4(v));
    }
}

// ---------------- K1: QKV node GEMM (fp32) ----------------------------------
__global__ __launch_bounds__(128) void qkv_kernel(
    const float* __restrict__ x,
    const float* __restrict__ Qw, const float* __restrict__ Qb,
    const float* __restrict__ Kw, const float* __restrict__ Kb,
    const float* __restrict__ Vw, const float* __restrict__ Vb)
{
    __shared__ float As[64][64];
    __shared__ float Bs[64][128];
    const int t   = threadIdx.x;
    const int m0  = blockIdx.x * 64;
    const int sel = blockIdx.y;
    const float* W  = (sel == 0) ? Qw : ((sel == 1) ? Kw : Vw);
    const float* Bv = (sel == 0) ? Qb : ((sel == 1) ? Kb : Vb);
    float* out      = (sel == 0) ? g_Q : ((sel == 1) ? g_K : g_V);

    #pragma unroll
    for (int l = 0; l < 8; l++) {
        int idx = l * 128 + t;
        int m  = idx >> 4;
        int k4 = (idx & 15) * 4;
        float4 v = make_float4(0.f, 0.f, 0.f, 0.f);
        if (m0 + m < NNODES) v = *(const float4*)(x + (size_t)(m0 + m) * 64 + k4);
        As[k4 + 0][m ^ (((k4 + 0) & 7) << 3)] = v.x;
        As[k4 + 1][m ^ (((k4 + 1) & 7) << 3)] = v.y;
        As[k4 + 2][m ^ (((k4 + 2) & 7) << 3)] = v.z;
        As[k4 + 3][m ^ (((k4 + 3) & 7) << 3)] = v.w;
    }
    #pragma unroll
    for (int l = 0; l < 16; l++) {
        int idx = l * 128 + t;
        int k  = idx >> 5;
        int n4 = (idx & 31) * 4;
        *(float4*)&Bs[k][n4] = *(const float4*)(W + (size_t)k * HD + n4);
    }
    __syncthreads();

    const int tx = t & 15, ty = t >> 4;
    float acc[8][8];
    #pragma unroll
    for (int i = 0; i < 8; i++)
        #pragma unroll
        for (int j = 0; j < 8; j++) acc[i][j] = 0.f;

    #pragma unroll 4
    for (int k = 0; k < 64; k++) {
        int ar = ((ty ^ (k & 7)) << 3);
        float4 a0 = *(const float4*)&As[k][ar];
        float4 a1 = *(const float4*)&As[k][ar + 4];
        float4 b0 = *(const float4*)&Bs[k][tx * 8];
        float4 b1 = *(const float4*)&Bs[k][tx * 8 + 4];
        float av[8] = {a0.x, a0.y, a0.z, a0.w, a1.x, a1.y, a1.z, a1.w};
        #pragma unroll
        for (int i = 0; i < 8; i++) {
            acc[i][0] += av[i] * b0.x; acc[i][1] += av[i] * b0.y;
            acc[i][2] += av[i] * b0.z; acc[i][3] += av[i] * b0.w;
            acc[i][4] += av[i] * b1.x; acc[i][5] += av[i] * b1.y;
            acc[i][6] += av[i] * b1.z; acc[i][7] += av[i] * b1.w;
        }
    }

    float4 bias0 = *(const float4*)(Bv + tx * 8);
    float4 bias1 = *(const float4*)(Bv + tx * 8 + 4);
    #pragma unroll
    for (int i = 0; i < 8; i++) {
        int gm = m0 + ty * 8 + i;
        if (gm < NNODES) {
            float4 o0 = make_float4(acc[i][0] + bias0.x, acc[i][1] + bias0.y,
                                    acc[i][2] + bias0.z, acc[i][3] + bias0.w);
            float4 o1 = make_float4(acc[i][4] + bias1.x, acc[i][5] + bias1.y,
                                    acc[i][6] + bias1.z, acc[i][7] + bias1.w);
            *(float4*)(out + (size_t)gm * HD + tx * 8)     = o0;
            *(float4*)(out + (size_t)gm * HD + tx * 8 + 4) = o1;
        }
    }
}

// ---------------- K2: edge GEMM via mma.sync bf16 hi/lo + epilogue ----------
// BM=128 edges, BN=128 cols (4 heads), K=64. 512 threads / 16 warps:
// warp = (row-group of 16) x (col-half of 64). acc = 32 regs/thread.
#define SM_A_HI 0
#define SM_A_LO 16384
#define SM_B_HI 32768
#define SM_B_LO 49152
#define ES_STRIDE 132
#define SMEM_EDGE_TOTAL (128 * ES_STRIDE * 4)   // 67584 >= 65536 tile bytes

__global__ __launch_bounds__(512, 2) void edge_kernel(
    const float* __restrict__ eattr, const int* __restrict__ eidx,
    const float* __restrict__ Eb, const float* __restrict__ Aw,
    float* __restrict__ outbuf)
{
    extern __shared__ char smem[];
    float* Es = (float*)smem;
    const uint32_t sbase = smem_u32(smem);
    const int t   = threadIdx.x;
    const int l   = t & 31;
    const int w   = t >> 5;
    const int m0  = blockIdx.x * 128;
    const int jb  = blockIdx.y;

    // ---- A tile: 128 edges x 64 K -> hi/lo bf16, swizzled (128B rows)
    #pragma unroll
    for (int it = 0; it < 4; it++) {
        int idx = it * 512 + t;
        int row = idx >> 4;
        int c4  = (idx & 15) * 4;
        const float4* ap = (const float4*)(eattr + (size_t)(m0 + row) * 64 + c4);
        float4 v = __ldcs(ap);
        unsigned int byte = (unsigned)row * 128 + (((unsigned)c4 * 2) ^ (((unsigned)row & 7) << 4));
        *(unsigned long long*)(smem + SM_A_HI + byte) = pack4_hi(v);
        *(unsigned long long*)(smem + SM_A_LO + byte) = pack4_hi(resid4(v));
    }
    // ---- B tiles: linear copy of pre-swizzled images (16KB each)
    {
        const ulonglong2* bh = (const ulonglong2*)(g_Bh + jb * 2048);
        const ulonglong2* bl = (const ulonglong2*)(g_Bl + jb * 2048);
        ulonglong2* dh = (ulonglong2*)(smem + SM_B_HI);
        ulonglong2* dl = (ulonglong2*)(smem + SM_B_LO);
        #pragma unroll
        for (int it = 0; it < 2; it++) {
            int idx = it * 512 + t;
            dh[idx] = bh[idx];
            dl[idx] = bl[idx];
        }
    }
    __syncthreads();

    // ---- MMA: warp w -> rows 16*(w&7).., cols 64*(w>>3)..
    float acc[8][4];
    #pragma unroll
    for (int j = 0; j < 8; j++)
        #pragma unroll
        for (int q = 0; q < 4; q++) acc[j][q] = 0.f;

    const int cg   = w >> 3;
    const int rw   = w & 7;
    const int m0w  = rw * 16;
    const int arow = m0w + (l & 15);
    const int asw  = ((l & 15) & 7) << 4;
    const int lx   = l & 7;
    const int bl15 = l & 15;
    const int jhi  = l >> 4;

    #pragma unroll
    for (int ks = 0; ks < 4; ks++) {
        uint32_t ah[4], al[4];
        uint32_t aoff = (unsigned)arow * 128 +
                        (((unsigned)(32 * ks + (l & 16))) ^ (unsigned)asw);
        ldmatrix_x4(ah, sbase + SM_A_HI + aoff);
        ldmatrix_x4(al, sbase + SM_A_LO + aoff);
        uint32_t brow_h = sbase + SM_B_HI + (unsigned)(16 * ks + bl15) * 256;
        uint32_t brow_l = sbase + SM_B_LO + (unsigned)(16 * ks + bl15) * 256;
        #pragma unroll
        for (int j = 0; j < 8; j += 2) {
            uint32_t boff = ((unsigned)((cg * 8 + j + jhi) ^ lx)) << 4;
            uint32_t bh[4], blo[4];
            ldmatrix_x4t(bh,  brow_h + boff);
            ldmatrix_x4t(blo, brow_l + boff);
            mma16816(acc[j],     ah, bh);
            mma16816(acc[j + 1], ah, bh + 2);
            mma16816(acc[j],     al, bh);
            mma16816(acc[j + 1], al, bh + 2);
            mma16816(acc[j],     ah, blo);
            mma16816(acc[j + 1], ah, blo + 2);
        }
    }

    // hoist gather indices to overlap with the Es overlay
    const int el  = t >> 2;          // edge slot 0..127
    const int e   = m0 + el;
    const int src = eidx[e];
    const int dst = eidx[NEDGES + e];

    __syncthreads();    // all warps done reading A/B; overlay Es

    // ---- write D fragments into Es[128][132]
    {
        const int g  = l >> 2;
        const int t2 = (l & 3) * 2;
        #pragma unroll
        for (int j = 0; j < 8; j++) {
            int col = cg * 64 + j * 8 + t2;
            *(float2*)&Es[(m0w + g) * ES_STRIDE + col]     = make_float2(acc[j][0], acc[j][1]);
            *(float2*)&Es[(m0w + g + 8) * ES_STRIDE + col] = make_float2(acc[j][2], acc[j][3]);
        }
    }
    __syncthreads();

    // ---- epilogue: 4 threads per edge, 1 head each
    const int hloc = t & 3;          // 0..3
    const int h    = jb * 4 + hloc;  // global head
    const int colK = h * 16;
    const float* Krow = g_K + (size_t)src * HD;
    const float* Qrow = g_Q + (size_t)dst * HD;
    float* oEp = outbuf + (size_t)OUT_OE + (size_t)e * HD;
    const float* EsRow = Es + el * ES_STRIDE;

    float sc[16];
    float a = 0.f;
    #pragma unroll
    for (int d4 = 0; d4 < 4; d4++) {
        float4 s1v = *(const float4*)(EsRow + hloc * 32 + d4 * 4);
        float4 s2v = *(const float4*)(EsRow + hloc * 32 + 16 + d4 * 4);
        float4 kv  = *(const float4*)(Krow + colK + d4 * 4);
        float4 qv  = *(const float4*)(Qrow + colK + d4 * 4);
        float s1a[4] = {s1v.x, s1v.y, s1v.z, s1v.w};
        float s2a[4] = {s2v.x, s2v.y, s2v.z, s2v.w};
        float kqa[4] = {kv.x + qv.x, kv.y + qv.y, kv.z + qv.z, kv.w + qv.w};
        #pragma unroll
        for (int q = 0; q < 4; q++) {
            int d = d4 * 4 + q;
            float s1 = s1a[q] + __ldg(Eb + h * 32 + d);
            float s2 = s2a[q] + __ldg(Eb + h * 32 + 16 + d);
            float pr = s1 * s2;
            float r  = sqrtf(fabsf(pr));
            sc[d] = copysignf(r, pr) + kqa[q];
            a += sc[d] * __ldg(Aw + d * 8 + h);
        }
    }
    __stcs((float4*)(oEp + colK),      *(float4*)&sc[0]);
    __stcs((float4*)(oEp + colK + 4),  *(float4*)&sc[4]);
    __stcs((float4*)(oEp + colK + 8),  *(float4*)&sc[8]);
    __stcs((float4*)(oEp + colK + 12), *(float4*)&sc[12]);

    a = fminf(fmaxf(a, -5.0f), 5.0f);
    g_w[(size_t)e * 8 + h] = expf(a);
}

// ---------------- K3: CSR build ---------------------------------------------
__global__ void zero_kernel()
{
    int i = blockIdx.x * blockDim.x + threadIdx.x;
    if (i < NNODES) g_deg[i] = 0;
}
__global__ void hist_kernel(const int* __restrict__ eidx)
{
    int e = blockIdx.x * blockDim.x + threadIdx.x;
    if (e < NEDGES) atomicAdd(&g_deg[eidx[NEDGES + e]], 1);
}
__global__ __launch_bounds__(SCAN_BLK) void scan1_kernel()
{
    __shared__ int warpsum[SCAN_BLK / 32];
    const int b = blockIdx.x, t = threadIdx.x;
    const int i = b * SCAN_BLK + t;
    int v = (i < NNODES) ? g_deg[i] : 0;
    int s = v;
    #pragma unroll
    for (int o = 1; o < 32; o <<= 1) {
        int u = __shfl_up_sync(0xffffffffu, s, o);
        if ((t & 31) >= o) s += u;
    }
    if ((t & 31) == 31) warpsum[t >> 5] = s;
    __syncthreads();
    if (t < SCAN_BLK / 32) {
        int ws = warpsum[t];
        #pragma unroll
        for (int o = 1; o < SCAN_BLK / 32; o <<= 1) {
            int u = __shfl_up_sync((1u << (SCAN_BLK / 32)) - 1u, ws, o);
            if (t >= o) ws += u;
        }
        warpsum[t] = ws;
    }
    __syncthreads();
    int excl = s - v + ((t >> 5) ? warpsum[(t >> 5) - 1] : 0);
    if (i < NNODES) g_off[i] = excl;
    if (t == SCAN_BLK - 1) g_bsum[b] = excl + v;
}
__global__ void scan2_kernel()
{
    __shared__ int ws[4];
    const int t = threadIdx.x;   // 128
    int v = (t < NSCB) ? g_bsum[t] : 0;
    int s = v;
    #pragma unroll
    for (int o = 1; o < 32; o <<= 1) {
        int u = __shfl_up_sync(0xffffffffu, s, o);
        if ((t & 31) >= o) s += u;
    }
    if ((t & 31) == 31) ws[t >> 5] = s;
    __syncthreads();
    if (t < 4) {
        int wv = ws[t];
        #pragma unroll
        for (int o = 1; o < 4; o <<= 1) {
            int u = __shfl_up_sync(0xfu, wv, o);
            if (t >= o) wv += u;
        }
        ws[t] = wv;
    }
    __syncthreads();
    int excl = s - v + ((t >> 5) ? ws[(t >> 5) - 1] : 0);
    if (t < NSCB) g_bpre[t] = excl;
    if (t == NSCB - 1) g_off[NNODES] = excl + v;
}
__global__ void scan3_kernel()
{
    int i = blockIdx.x * blockDim.x + threadIdx.x;
    if (i < NNODES) {
        int o = g_off[i] + g_bpre[i >> 8];
        g_off[i] = o;
        g_cursor[i] = o;
    }
}
__global__ void scatter_kernel(const int* __restrict__ eidx)
{
    int e = blockIdx.x * blockDim.x + threadIdx.x;
    if (e < NEDGES) {
        int dst = eidx[NEDGES + e];
        int p = atomicAdd(&g_cursor[dst], 1);
        g_csr[p] = make_int2(e, eidx[e]);
    }
}

// ---------------- K4: fused softmax + aggregation ---------------------------
__global__ __launch_bounds__(128) void node_kernel(
    const float* __restrict__ VeRow,
    const float* __restrict__ oE,
    float* __restrict__ n_out)
{
    __shared__ int2  stage[128];
    __shared__ float rowS[8][17];
    const int n = blockIdx.x;
    const int t = threadIdx.x;
    const int h = t >> 4, c = t & 15;
    const int beg = g_off[n], end = g_off[n + 1];

    float den = 0.f, accV = 0.f, accR = 0.f;
    for (int base = beg; base < end; base += 128) {
        int cnt = min(128, end - base);
        __syncthreads();
        if (t < cnt) stage[t] = g_csr[base + t];
        __syncthreads();
        #pragma unroll 4
        for (int i = 0; i < cnt; i++) {
            int e   = stage[i].x;
            int src = stage[i].y;
            float wv = g_w[(size_t)e * 8 + h];
            den  += wv;
            accV += wv * g_V[(size_t)src * HD + t];
            accR += wv * __ldcs(oE + (size_t)e * HD + t);
        }
    }
    float inv = 1.f / (den + 1e-16f);

    rowS[h][c] = accR * inv;
    __syncthreads();
    float r = 0.f;
    #pragma unroll
    for (int d = 0; d < 16; d++)
        r += rowS[h][d] * VeRow[d * HD + h * 16 + c];

    n_out[(size_t)n * HD + t] = accV * inv + r;
}

// ---------------- launch -----------------------------------------------------
extern "C" void kernel_launch(void* const* d_in, const int* in_sizes, int n_in,
                              void* d_out, int out_size)
{
    const float* x     = (const float*)d_in[0];
    const float* eattr = (const float*)d_in[1];
    const int*   eidx  = (const int*)  d_in[2];
    const float* Qw = (const float*)d_in[3];  const float* Qb = (const float*)d_in[4];
    const float* Kw = (const float*)d_in[5];  const float* Kb = (const float*)d_in[6];
    const float* Ew = (const float*)d_in[7];  const float* Eb = (const float*)d_in[8];
    const float* Vw = (const float*)d_in[9];  const float* Vb = (const float*)d_in[10];
    const float* Aw = (const float*)d_in[11]; const float* VeRow = (const float*)d_in[12];
    float* out = (float*)d_out;

    cudaFuncSetAttribute(edge_kernel, cudaFuncAttributeMaxDynamicSharedMemorySize,
                         SMEM_EDGE_TOTAL);

    bprep_kernel<<<2, 256>>>(Ew);                                           // 1
    zero_kernel<<<(NNODES + 255) / 256, 256>>>();                           // 2
    qkv_kernel<<<dim3((NNODES + 63) / 64, 3), 128>>>(x, Qw, Qb, Kw, Kb, Vw, Vb); // 3
    edge_kernel<<<dim3(NEDGES / 128, 2), 512, SMEM_EDGE_TOTAL>>>(eattr, eidx, Eb, Aw, out); // 4 (profiled)
    hist_kernel<<<(NEDGES + 255) / 256, 256>>>(eidx);                       // 5
    scan1_kernel<<<NSCB, SCAN_BLK>>>();                                     // 6
    scan2_kernel<<<1, 128>>>();                                             // 7
    scan3_kernel<<<(NNODES + 255) / 256, 256>>>();                          // 8
    scatter_kernel<<<(NEDGES + 255) / 256, 256>>>(eidx);                    // 9
    node_kernel<<<NNODES, 128>>>(VeRow, out + OUT_OE, out);                 // 10
}

// round 7
// speedup vs baseline: 2.3547x; 1.2804x over previous
#include <cuda_runtime.h>
#include <cuda_bf16.h>
#include <math.h>
#include <stdint.h>

#define NNODES 20000
#define NEDGES 320000
#define HD 128
#define OUT_OE (NNODES * HD)

// ---------------- scratch ----------------------------------------------------
__device__ float g_Q[NNODES * HD];
__device__ float g_K[NNODES * HD];
__device__ float g_V[NNODES * HD];
__device__ float g_w[NEDGES * 8];
__device__ int   g_deg[NNODES];
__device__ int   g_off[NNODES + 1];
__device__ int   g_cursor[NNODES];
__device__ int2  g_csr[NEDGES];
#define SCAN_BLK 256
#define NSCB ((NNODES + SCAN_BLK - 1) / SCAN_BLK)
__device__ int   g_bsum[NSCB];
__device__ int   g_bpre[NSCB];
// pre-swizzled bf16 B images: [2 halves][64 k][128 n], 16KB per half per img
__device__ unsigned long long g_Bh[4096];
__device__ unsigned long long g_Bl[4096];

// ---------------- helpers ----------------------------------------------------
__device__ __forceinline__ uint32_t smem_u32(const void* p) {
    uint32_t a;
    asm("{ .reg .u64 t; cvta.to.shared.u64 t, %1; cvt.u32.u64 %0, t; }" : "=r"(a) : "l"(p));
    return a;
}
__device__ __forceinline__ unsigned long long pack4_hi(float4 v) {
    unsigned short h0 = __bfloat16_as_ushort(__float2bfloat16(v.x));
    unsigned short h1 = __bfloat16_as_ushort(__float2bfloat16(v.y));
    unsigned short h2 = __bfloat16_as_ushort(__float2bfloat16(v.z));
    unsigned short h3 = __bfloat16_as_ushort(__float2bfloat16(v.w));
    return (unsigned long long)h0 | ((unsigned long long)h1 << 16) |
           ((unsigned long long)h2 << 32) | ((unsigned long long)h3 << 48);
}
__device__ __forceinline__ float4 resid4(float4 v) {
    return make_float4(
        v.x - __bfloat162float(__float2bfloat16(v.x)),
        v.y - __bfloat162float(__float2bfloat16(v.y)),
        v.z - __bfloat162float(__float2bfloat16(v.z)),
        v.w - __bfloat162float(__float2bfloat16(v.w)));
}
__device__ __forceinline__ void ldmatrix_x4(uint32_t* r, uint32_t addr) {
    asm volatile("ldmatrix.sync.aligned.m8n8.x4.shared.b16 {%0,%1,%2,%3}, [%4];"
                 : "=r"(r[0]), "=r"(r[1]), "=r"(r[2]), "=r"(r[3]) : "r"(addr));
}
__device__ __forceinline__ void ldmatrix_x4t(uint32_t* r, uint32_t addr) {
    asm volatile("ldmatrix.sync.aligned.m8n8.x4.trans.shared.b16 {%0,%1,%2,%3}, [%4];"
                 : "=r"(r[0]), "=r"(r[1]), "=r"(r[2]), "=r"(r[3]) : "r"(addr));
}
__device__ __forceinline__ void mma16816(float* c, const uint32_t* a, const uint32_t* b) {
    asm volatile(
        "mma.sync.aligned.m16n8k16.row.col.f32.bf16.bf16.f32 "
        "{%0,%1,%2,%3}, {%4,%5,%6,%7}, {%8,%9}, {%0,%1,%2,%3};"
        : "+f"(c[0]), "+f"(c[1]), "+f"(c[2]), "+f"(c[3])
        : "r"(a[0]), "r"(a[1]), "r"(a[2]), "r"(a[3]), "r"(b[0]), "r"(b[1]));
}

// ---------------- K0: precompute bf16 hi/lo images of Ew --------------------
__global__ void bprep_kernel(const float* __restrict__ Ew)
{
    const int jb = blockIdx.x;
    const int t  = threadIdx.x;   // 256
    for (int it = 0; it < 8; it++) {
        int idx = it * 256 + t;          // 0..2047
        int k   = idx >> 5;              // 0..63
        int n4  = (idx & 31) * 4;        // 0..124
        const float* p = Ew + (size_t)k * 256 + jb * 128 + n4;
        float4 v = make_float4(p[0], p[1], p[2], p[3]);
        unsigned int byte = (unsigned)k * 256 + (((unsigned)n4 * 2) ^ (((unsigned)k & 7) << 4));
        unsigned int i8 = (jb * 16384 + byte) >> 3;
        g_Bh[i8] = pack4_hi(v);
        g_Bl[i8] = pack4_hi(resid4(v));
    }
}

// ---------------- K1: QKV node GEMM (fp32) ----------------------------------
__global__ __launch_bounds__(128) void qkv_kernel(
    const float* __restrict__ x,
    const float* __restrict__ Qw, const float* __restrict__ Qb,
    const float* __restrict__ Kw, const float* __restrict__ Kb,
    const float* __restrict__ Vw, const float* __restrict__ Vb)
{
    __shared__ float As[64][64];
    __shared__ float Bs[64][128];
    const int t   = threadIdx.x;
    const int m0  = blockIdx.x * 64;
    const int sel = blockIdx.y;
    const float* W  = (sel == 0) ? Qw : ((sel == 1) ? Kw : Vw);
    const float* Bv = (sel == 0) ? Qb : ((sel == 1) ? Kb : Vb);
    float* out      = (sel == 0) ? g_Q : ((sel == 1) ? g_K : g_V);

    #pragma unroll
    for (int l = 0; l < 8; l++) {
        int idx = l * 128 + t;
        int m  = idx >> 4;
        int k4 = (idx & 15) * 4;
        float4 v = make_float4(0.f, 0.f, 0.f, 0.f);
        if (m0 + m < NNODES) v = *(const float4*)(x + (size_t)(m0 + m) * 64 + k4);
        As[k4 + 0][m ^ (((k4 + 0) & 7) << 3)] = v.x;
        As[k4 + 1][m ^ (((k4 + 1) & 7) << 3)] = v.y;
        As[k4 + 2][m ^ (((k4 + 2) & 7) << 3)] = v.z;
        As[k4 + 3][m ^ (((k4 + 3) & 7) << 3)] = v.w;
    }
    #pragma unroll
    for (int l = 0; l < 16; l++) {
        int idx = l * 128 + t;
        int k  = idx >> 5;
        int n4 = (idx & 31) * 4;
        *(float4*)&Bs[k][n4] = *(const float4*)(W + (size_t)k * HD + n4);
    }
    __syncthreads();

    const int tx = t & 15, ty = t >> 4;
    float acc[8][8];
    #pragma unroll
    for (int i = 0; i < 8; i++)
        #pragma unroll
        for (int j = 0; j < 8; j++) acc[i][j] = 0.f;

    #pragma unroll 4
    for (int k = 0; k < 64; k++) {
        int ar = ((ty ^ (k & 7)) << 3);
        float4 a0 = *(const float4*)&As[k][ar];
        float4 a1 = *(const float4*)&As[k][ar + 4];
        float4 b0 = *(const float4*)&Bs[k][tx * 8];
        float4 b1 = *(const float4*)&Bs[k][tx * 8 + 4];
        float av[8] = {a0.x, a0.y, a0.z, a0.w, a1.x, a1.y, a1.z, a1.w};
        #pragma unroll
        for (int i = 0; i < 8; i++) {
            acc[i][0] += av[i] * b0.x; acc[i][1] += av[i] * b0.y;
            acc[i][2] += av[i] * b0.z; acc[i][3] += av[i] * b0.w;
            acc[i][4] += av[i] * b1.x; acc[i][5] += av[i] * b1.y;
            acc[i][6] += av[i] * b1.z; acc[i][7] += av[i] * b1.w;
        }
    }

    float4 bias0 = *(const float4*)(Bv + tx * 8);
    float4 bias1 = *(const float4*)(Bv + tx * 8 + 4);
    #pragma unroll
    for (int i = 0; i < 8; i++) {
        int gm = m0 + ty * 8 + i;
        if (gm < NNODES) {
            float4 o0 = make_float4(acc[i][0] + bias0.x, acc[i][1] + bias0.y,
                                    acc[i][2] + bias0.z, acc[i][3] + bias0.w);
            float4 o1 = make_float4(acc[i][4] + bias1.x, acc[i][5] + bias1.y,
                                    acc[i][6] + bias1.z, acc[i][7] + bias1.w);
            *(float4*)(out + (size_t)gm * HD + tx * 8)     = o0;
            *(float4*)(out + (size_t)gm * HD + tx * 8 + 4) = o1;
        }
    }
}

// ---------------- K2: edge GEMM via mma.sync bf16 hi/lo + reg epilogue ------
// BM=128 edges, BN=128 cols (4 heads), K=64. 512 threads / 16 warps:
// warp = (row-group of 32) x (head of 32 cols). Epilogue fully in registers.
#define SM_A_HI 0
#define SM_A_LO 16384
#define SM_B_HI 32768
#define SM_B_LO 49152
#define SMEM_EDGE_TOTAL 65536

__global__ __launch_bounds__(512, 2) void edge_kernel(
    const float* __restrict__ eattr, const int* __restrict__ eidx,
    const float* __restrict__ Eb, const float* __restrict__ Aw,
    float* __restrict__ outbuf)
{
    extern __shared__ char smem[];
    const uint32_t sbase = smem_u32(smem);
    const int t   = threadIdx.x;
    const int l   = t & 31;
    const int w   = t >> 5;
    const int m0  = blockIdx.x * 128;
    const int jb  = blockIdx.y;

    // ---- A tile: 128 edges x 64 K -> hi/lo bf16, swizzled (128B rows)
    #pragma unroll
    for (int it = 0; it < 4; it++) {
        int idx = it * 512 + t;
        int row = idx >> 4;
        int c4  = (idx & 15) * 4;
        const float4* ap = (const float4*)(eattr + (size_t)(m0 + row) * 64 + c4);
        float4 v = __ldcs(ap);
        unsigned int byte = (unsigned)row * 128 + (((unsigned)c4 * 2) ^ (((unsigned)row & 7) << 4));
        *(unsigned long long*)(smem + SM_A_HI + byte) = pack4_hi(v);
        *(unsigned long long*)(smem + SM_A_LO + byte) = pack4_hi(resid4(v));
    }
    // ---- B tiles: linear copy of pre-swizzled images (16KB each)
    {
        const ulonglong2* bh = (const ulonglong2*)(g_Bh + jb * 2048);
        const ulonglong2* bl = (const ulonglong2*)(g_Bl + jb * 2048);
        ulonglong2* dh = (ulonglong2*)(smem + SM_B_HI);
        ulonglong2* dl = (ulonglong2*)(smem + SM_B_LO);
        #pragma unroll
        for (int it = 0; it < 2; it++) {
            int idx = it * 512 + t;
            dh[idx] = bh[idx];
            dl[idx] = bl[idx];
        }
    }
    __syncthreads();

    // ---- MMA: warp w -> rows 32*(w>>2)..+31, head (w&3)
    const int rg   = w >> 2;
    const int cgg  = w & 3;
    const int g    = l >> 2;
    const int t2   = (l & 3) * 2;
    const int lx   = l & 7;
    const int bl15 = l & 15;
    const int jhi  = l >> 4;
    const int arow = rg * 32 + (l & 15);
    const int asw  = ((l & 15) & 7) << 4;

    float acc[2][4][4];
    #pragma unroll
    for (int m = 0; m < 2; m++)
        #pragma unroll
        for (int n = 0; n < 4; n++)
            #pragma unroll
            for (int q = 0; q < 4; q++) acc[m][n][q] = 0.f;

    #pragma unroll
    for (int ks = 0; ks < 4; ks++) {
        uint32_t ah[2][4], al[2][4];
        #pragma unroll
        for (int m = 0; m < 2; m++) {
            uint32_t aoff = (unsigned)(arow + m * 16) * 128 +
                            (((unsigned)(32 * ks + (l & 16))) ^ (unsigned)asw);
            ldmatrix_x4(ah[m], sbase + SM_A_HI + aoff);
            ldmatrix_x4(al[m], sbase + SM_A_LO + aoff);
        }
        uint32_t browoff = (unsigned)(16 * ks + bl15) * 256;
        #pragma unroll
        for (int np = 0; np < 2; np++) {
            uint32_t boff = ((unsigned)((cgg * 4 + np * 2 + jhi) ^ lx)) << 4;
            uint32_t bh[4], blo[4];
            ldmatrix_x4t(bh,  sbase + SM_B_HI + browoff + boff);
            ldmatrix_x4t(blo, sbase + SM_B_LO + browoff + boff);
            #pragma unroll
            for (int m = 0; m < 2; m++) {
                mma16816(acc[m][np * 2],     ah[m], bh);
                mma16816(acc[m][np * 2 + 1], ah[m], bh + 2);
                mma16816(acc[m][np * 2],     al[m], bh);
                mma16816(acc[m][np * 2 + 1], al[m], bh + 2);
                mma16816(acc[m][np * 2],     ah[m], blo);
                mma16816(acc[m][np * 2 + 1], ah[m], blo + 2);
            }
        }
    }

    // ---- epilogue (in registers; no syncthreads needed) ----
    // thread owns rows {g, g+8, 16+g, 24+g} (local), cols d = {t2,t2+1,8+t2,8+t2+1}
    const int h    = jb * 4 + cgg;
    const int colK = h * 16;

    // hoisted small tables
    const float eb1a = __ldg(Eb + h * 32 + t2);
    const float eb1b = __ldg(Eb + h * 32 + t2 + 1);
    const float eb1c = __ldg(Eb + h * 32 + 8 + t2);
    const float eb1d = __ldg(Eb + h * 32 + 8 + t2 + 1);
    const float eb2a = __ldg(Eb + h * 32 + 16 + t2);
    const float eb2b = __ldg(Eb + h * 32 + 16 + t2 + 1);
    const float eb2c = __ldg(Eb + h * 32 + 24 + t2);
    const float eb2d = __ldg(Eb + h * 32 + 24 + t2 + 1);
    const float aw0 = __ldg(Aw + (t2)     * 8 + h);
    const float aw1 = __ldg(Aw + (t2 + 1) * 8 + h);
    const float aw8 = __ldg(Aw + (8 + t2)     * 8 + h);
    const float aw9 = __ldg(Aw + (8 + t2 + 1) * 8 + h);

    float apart[4];
    int   erow[4];
    #pragma unroll
    for (int r = 0; r < 4; r++) {
        const int m  = r >> 1;
        const int qh = r & 1;
        const int rowl = m * 16 + g + qh * 8;
        const int e  = m0 + rg * 32 + rowl;
        erow[r] = e;
        const int src = eidx[e];
        const int dst = eidx[NEDGES + e];
        const float* Krow = g_K + (size_t)src * HD + colK;
        const float* Qrow = g_Q + (size_t)dst * HD + colK;
        float* oEp = outbuf + (size_t)OUT_OE + (size_t)e * HD + colK;

        float a = 0.f;
        // n = 0 : d = t2, t2+1
        {
            float s1a = acc[m][0][qh * 2]     + eb1a;
            float s1b = acc[m][0][qh * 2 + 1] + eb1b;
            float s2a = acc[m][2][qh * 2]     + eb2a;
            float s2b = acc[m][2][qh * 2 + 1] + eb2b;
            float2 kv = *(const float2*)(Krow + t2);
            float2 qv = *(const float2*)(Qrow + t2);
            float p0 = s1a * s2a, p1 = s1b * s2b;
            float sc0 = copysignf(sqrtf(fabsf(p0)), p0) + kv.x + qv.x;
            float sc1 = copysignf(sqrtf(fabsf(p1)), p1) + kv.y + qv.y;
            __stcs((float2*)(oEp + t2), make_float2(sc0, sc1));
            a += sc0 * aw0 + sc1 * aw1;
        }
        // n = 1 : d = 8+t2, 8+t2+1
        {
            float s1a = acc[m][1][qh * 2]     + eb1c;
            float s1b = acc[m][1][qh * 2 + 1] + eb1d;
            float s2a = acc[m][3][qh * 2]     + eb2c;
            float s2b = acc[m][3][qh * 2 + 1] + eb2d;
            float2 kv = *(const float2*)(Krow + 8 + t2);
            float2 qv = *(const float2*)(Qrow + 8 + t2);
            float p0 = s1a * s2a, p1 = s1b * s2b;
            float sc0 = copysignf(sqrtf(fabsf(p0)), p0) + kv.x + qv.x;
            float sc1 = copysignf(sqrtf(fabsf(p1)), p1) + kv.y + qv.y;
            __stcs((float2*)(oEp + 8 + t2), make_float2(sc0, sc1));
            a += sc0 * aw8 + sc1 * aw9;
        }
        apart[r] = a;
    }

    // reduce a over the 4 lanes sharing each row (t2 = 0,2,4,6)
    #pragma unroll
    for (int r = 0; r < 4; r++) {
        apart[r] += __shfl_xor_sync(0xffffffffu, apart[r], 1);
        apart[r] += __shfl_xor_sync(0xffffffffu, apart[r], 2);
    }
    if ((l & 3) == 0) {
        #pragma unroll
        for (int r = 0; r < 4; r++) {
            float a = fminf(fmaxf(apart[r], -5.0f), 5.0f);
            g_w[(size_t)erow[r] * 8 + h] = expf(a);
        }
    }
}

// ---------------- K3: CSR build ---------------------------------------------
__global__ void zero_kernel()
{
    int i = blockIdx.x * blockDim.x + threadIdx.x;
    if (i < NNODES) g_deg[i] = 0;
}
__global__ void hist_kernel(const int* __restrict__ eidx)
{
    int e = blockIdx.x * blockDim.x + threadIdx.x;
    if (e < NEDGES) atomicAdd(&g_deg[eidx[NEDGES + e]], 1);
}
__global__ __launch_bounds__(SCAN_BLK) void scan1_kernel()
{
    __shared__ int warpsum[SCAN_BLK / 32];
    const int b = blockIdx.x, t = threadIdx.x;
    const int i = b * SCAN_BLK + t;
    int v = (i < NNODES) ? g_deg[i] : 0;
    int s = v;
    #pragma unroll
    for (int o = 1; o < 32; o <<= 1) {
        int u = __shfl_up_sync(0xffffffffu, s, o);
        if ((t & 31) >= o) s += u;
    }
    if ((t & 31) == 31) warpsum[t >> 5] = s;
    __syncthreads();
    if (t < SCAN_BLK / 32) {
        int ws = warpsum[t];
        #pragma unroll
        for (int o = 1; o < SCAN_BLK / 32; o <<= 1) {
            int u = __shfl_up_sync((1u << (SCAN_BLK / 32)) - 1u, ws, o);
            if (t >= o) ws += u;
        }
        warpsum[t] = ws;
    }
    __syncthreads();
    int excl = s - v + ((t >> 5) ? warpsum[(t >> 5) - 1] : 0);
    if (i < NNODES) g_off[i] = excl;
    if (t == SCAN_BLK - 1) g_bsum[b] = excl + v;
}
__global__ void scan2_kernel()
{
    __shared__ int ws[4];
    const int t = threadIdx.x;   // 128
    int v = (t < NSCB) ? g_bsum[t] : 0;
    int s = v;
    #pragma unroll
    for (int o = 1; o < 32; o <<= 1) {
        int u = __shfl_up_sync(0xffffffffu, s, o);
        if ((t & 31) >= o) s += u;
    }
    if ((t & 31) == 31) ws[t >> 5] = s;
    __syncthreads();
    if (t < 4) {
        int wv = ws[t];
        #pragma unroll
        for (int o = 1; o < 4; o <<= 1) {
            int u = __shfl_up_sync(0xfu, wv, o);
            if (t >= o) wv += u;
        }
        ws[t] = wv;
    }
    __syncthreads();
    int excl = s - v + ((t >> 5) ? ws[(t >> 5) - 1] : 0);
    if (t < NSCB) g_bpre[t] = excl;
    if (t == NSCB - 1) g_off[NNODES] = excl + v;
}
__global__ void scan3_kernel()
{
    int i = blockIdx.x * blockDim.x + threadIdx.x;
    if (i < NNODES) {
        int o = g_off[i] + g_bpre[i >> 8];
        g_off[i] = o;
        g_cursor[i] = o;
    }
}
__global__ void scatter_kernel(const int* __restrict__ eidx)
{
    int e = blockIdx.x * blockDim.x + threadIdx.x;
    if (e < NEDGES) {
        int dst = eidx[NEDGES + e];
        int p = atomicAdd(&g_cursor[dst], 1);
        g_csr[p] = make_int2(e, eidx[e]);
    }
}

// ---------------- K4: fused softmax + aggregation ---------------------------
__global__ __launch_bounds__(128) void node_kernel(
    const float* __restrict__ VeRow,
    const float* __restrict__ oE,
    float* __restrict__ n_out)
{
    __shared__ int2  stage[128];
    __shared__ float rowS[8][17];
    const int n = blockIdx.x;
    const int t = threadIdx.x;
    const int h = t >> 4, c = t & 15;
    const int beg = g_off[n], end = g_off[n + 1];

    float den = 0.f, accV = 0.f, accR = 0.f;
    for (int base = beg; base < end; base += 128) {
        int cnt = min(128, end - base);
        __syncthreads();
        if (t < cnt) stage[t] = g_csr[base + t];
        __syncthreads();
        #pragma unroll 4
        for (int i = 0; i < cnt; i++) {
            int e   = stage[i].x;
            int src = stage[i].y;
            float wv = g_w[(size_t)e * 8 + h];
            den  += wv;
            accV += wv * g_V[(size_t)src * HD + t];
            accR += wv * __ldcs(oE + (size_t)e * HD + t);
        }
    }
    float inv = 1.f / (den + 1e-16f);

    rowS[h][c] = accR * inv;
    __syncthreads();
    float r = 0.f;
    #pragma unroll
    for (int d = 0; d < 16; d++)
        r += rowS[h][d] * VeRow[d * HD + h * 16 + c];

    n_out[(size_t)n * HD + t] = accV * inv + r;
}

// ---------------- launch -----------------------------------------------------
extern "C" void kernel_launch(void* const* d_in, const int* in_sizes, int n_in,
                              void* d_out, int out_size)
{
    const float* x     = (const float*)d_in[0];
    const float* eattr = (const float*)d_in[1];
    const int*   eidx  = (const int*)  d_in[2];
    const float* Qw = (const float*)d_in[3];  const float* Qb = (const float*)d_in[4];
    const float* Kw = (const float*)d_in[5];  const float* Kb = (const float*)d_in[6];
    const float* Ew = (const float*)d_in[7];  const float* Eb = (const float*)d_in[8];
    const float* Vw = (const float*)d_in[9];  const float* Vb = (const float*)d_in[10];
    const float* Aw = (const float*)d_in[11]; const float* VeRow = (const float*)d_in[12];
    float* out = (float*)d_out;

    cudaFuncSetAttribute(edge_kernel, cudaFuncAttributeMaxDynamicSharedMemorySize,
                         SMEM_EDGE_TOTAL);

    bprep_kernel<<<2, 256>>>(Ew);                                           // 1
    zero_kernel<<<(NNODES + 255) / 256, 256>>>();                           // 2
    qkv_kernel<<<dim3((NNODES + 63) / 64, 3), 128>>>(x, Qw, Qb, Kw, Kb, Vw, Vb); // 3
    edge_kernel<<<dim3(NEDGES / 128, 2), 512, SMEM_EDGE_TOTAL>>>(eattr, eidx, Eb, Aw, out); // 4 (profiled)
    hist_kernel<<<(NEDGES + 255) / 256, 256>>>(eidx);                       // 5
    scan1_kernel<<<NSCB, SCAN_BLK>>>();                                     // 6
    scan2_kernel<<<1, 128>>>();                                             // 7
    scan3_kernel<<<(NNODES + 255) / 256, 256>>>();                          // 8
    scatter_kernel<<<(NEDGES + 255) / 256, 256>>>(eidx);                    // 9
    node_kernel<<<NNODES, 128>>>(VeRow, out + OUT_OE, out);                 // 10
}

// round 8
// speedup vs baseline: 2.4815x; 1.0539x over previous
#include <cuda_runtime.h>
#include <cuda_bf16.h>
#include <math.h>
#include <stdint.h>

#define NNODES 20000
#define NEDGES 320000
#define HD 128
#define OUT_OE (NNODES * HD)

// ---------------- scratch ----------------------------------------------------
__device__ float g_Q[NNODES * HD];
__device__ float g_K[NNODES * HD];
__device__ float g_V[NNODES * HD];
__device__ float g_w[NEDGES * 8];
__device__ int   g_deg[NNODES];
__device__ int   g_off[NNODES + 1];
__device__ int   g_cursor[NNODES];
__device__ int2  g_csr[NEDGES];
#define SCAN_BLK 256
#define NSCB ((NNODES + SCAN_BLK - 1) / SCAN_BLK)
__device__ int   g_bsum[NSCB];
__device__ int   g_bpre[NSCB];
// pre-swizzled bf16 images
__device__ unsigned long long g_Bh[4096];        // Ew: [64 k][256 n], 32KB
__device__ unsigned long long g_Bl[4096];
__device__ unsigned long long g_Wh[3 * 2048];    // Qw/Kw/Vw: [64 k][128 n], 16KB each
__device__ unsigned long long g_Wl[3 * 2048];

// ---------------- helpers ----------------------------------------------------
__device__ __forceinline__ uint32_t smem_u32(const void* p) {
    uint32_t a;
    asm("{ .reg .u64 t; cvta.to.shared.u64 t, %1; cvt.u32.u64 %0, t; }" : "=r"(a) : "l"(p));
    return a;
}
__device__ __forceinline__ unsigned long long pack4_hi(float4 v) {
    unsigned short h0 = __bfloat16_as_ushort(__float2bfloat16(v.x));
    unsigned short h1 = __bfloat16_as_ushort(__float2bfloat16(v.y));
    unsigned short h2 = __bfloat16_as_ushort(__float2bfloat16(v.z));
    unsigned short h3 = __bfloat16_as_ushort(__float2bfloat16(v.w));
    return (unsigned long long)h0 | ((unsigned long long)h1 << 16) |
           ((unsigned long long)h2 << 32) | ((unsigned long long)h3 << 48);
}
__device__ __forceinline__ float4 resid4(float4 v) {
    return make_float4(
        v.x - __bfloat162float(__float2bfloat16(v.x)),
        v.y - __bfloat162float(__float2bfloat16(v.y)),
        v.z - __bfloat162float(__float2bfloat16(v.z)),
        v.w - __bfloat162float(__float2bfloat16(v.w)));
}
__device__ __forceinline__ void ldmatrix_x4(uint32_t* r, uint32_t addr) {
    asm volatile("ldmatrix.sync.aligned.m8n8.x4.shared.b16 {%0,%1,%2,%3}, [%4];"
                 : "=r"(r[0]), "=r"(r[1]), "=r"(r[2]), "=r"(r[3]) : "r"(addr));
}
__device__ __forceinline__ void ldmatrix_x4t(uint32_t* r, uint32_t addr) {
    asm volatile("ldmatrix.sync.aligned.m8n8.x4.trans.shared.b16 {%0,%1,%2,%3}, [%4];"
                 : "=r"(r[0]), "=r"(r[1]), "=r"(r[2]), "=r"(r[3]) : "r"(addr));
}
__device__ __forceinline__ void mma16816(float* c, const uint32_t* a, const uint32_t* b) {
    asm volatile(
        "mma.sync.aligned.m16n8k16.row.col.f32.bf16.bf16.f32 "
        "{%0,%1,%2,%3}, {%4,%5,%6,%7}, {%8,%9}, {%0,%1,%2,%3};"
        : "+f"(c[0]), "+f"(c[1]), "+f"(c[2]), "+f"(c[3])
        : "r"(a[0]), "r"(a[1]), "r"(a[2]), "r"(a[3]), "r"(b[0]), "r"(b[1]));
}
__device__ __forceinline__ float sqrt_approx(float x) {
    float r;
    asm("sqrt.approx.f32 %0, %1;" : "=f"(r) : "f"(x));
    return r;
}

// ---------------- K0a: Ew -> bf16 hi/lo pre-swizzled image [64][256] --------
__global__ void bprep_kernel(const float* __restrict__ Ew)
{
    const int jb = blockIdx.x;    // 0..3 (64-col groups)
    const int t  = threadIdx.x;   // 256
    #pragma unroll
    for (int it = 0; it < 4; it++) {
        int idx = it * 256 + t;          // 0..1023
        int k   = idx >> 4;              // 0..63
        int n4l = (idx & 15) * 4;        // 0..60
        int n   = jb * 64 + n4l;
        const float* p = Ew + (size_t)k * 256 + n;
        float4 v = make_float4(p[0], p[1], p[2], p[3]);
        unsigned int byte = (unsigned)k * 512 + (((unsigned)n * 2) ^ (((unsigned)k & 7) << 4));
        unsigned int i8 = byte >> 3;
        g_Bh[i8] = pack4_hi(v);
        g_Bl[i8] = pack4_hi(resid4(v));
    }
}

// ---------------- K0b: Qw/Kw/Vw -> bf16 hi/lo images [64][128] each ---------
__global__ void wprep_kernel(const float* __restrict__ Qw,
                             const float* __restrict__ Kw,
                             const float* __restrict__ Vw)
{
    const int sel = blockIdx.x;   // 0..2
    const float* W = (sel == 0) ? Qw : ((sel == 1) ? Kw : Vw);
    const int t = threadIdx.x;    // 256
    #pragma unroll
    for (int it = 0; it < 8; it++) {
        int idx = it * 256 + t;          // 0..2047
        int k   = idx >> 5;              // 0..63
        int n4  = (idx & 31) * 4;        // 0..124
        const float* p = W + (size_t)k * 128 + n4;
        float4 v = make_float4(p[0], p[1], p[2], p[3]);
        unsigned int byte = (unsigned)k * 256 + (((unsigned)n4 * 2) ^ (((unsigned)k & 7) << 4));
        unsigned int i8 = ((unsigned)sel * 16384 + byte) >> 3;
        g_Wh[i8] = pack4_hi(v);
        g_Wl[i8] = pack4_hi(resid4(v));
    }
}

// ---------------- K1: QKV node GEMM via mma.sync bf16 hi/lo -----------------
// BM=128 nodes, BN=128, K=64. 512 threads / 16 warps; warp = 32 rows x 32 cols.
#define QSM_A_HI 0
#define QSM_A_LO 16384
#define QSM_B_HI 32768
#define QSM_B_LO 49152
#define SMEM_QKV_TOTAL 65536

__global__ __launch_bounds__(512, 2) void qkv_kernel(
    const float* __restrict__ x,
    const float* __restrict__ Qb, const float* __restrict__ Kb,
    const float* __restrict__ Vb)
{
    extern __shared__ char smem[];
    const uint32_t sbase = smem_u32(smem);
    const int t   = threadIdx.x;
    const int l   = t & 31;
    const int w   = t >> 5;
    const int m0  = blockIdx.x * 128;
    const int sel = blockIdx.y;
    const float* Bv = (sel == 0) ? Qb : ((sel == 1) ? Kb : Vb);
    float* out      = (sel == 0) ? g_Q : ((sel == 1) ? g_K : g_V);

    // A tile: 128 nodes x 64 -> hi/lo bf16, swizzled (guarded)
    #pragma unroll
    for (int it = 0; it < 4; it++) {
        int idx = it * 512 + t;
        int row = idx >> 4;
        int c4  = (idx & 15) * 4;
        float4 v = make_float4(0.f, 0.f, 0.f, 0.f);
        if (m0 + row < NNODES) v = *(const float4*)(x + (size_t)(m0 + row) * 64 + c4);
        unsigned int byte = (unsigned)row * 128 + (((unsigned)c4 * 2) ^ (((unsigned)row & 7) << 4));
        *(unsigned long long*)(smem + QSM_A_HI + byte) = pack4_hi(v);
        *(unsigned long long*)(smem + QSM_A_LO + byte) = pack4_hi(resid4(v));
    }
    // B image copy (16KB each)
    {
        const ulonglong2* bh = (const ulonglong2*)(g_Wh + sel * 2048);
        const ulonglong2* bl = (const ulonglong2*)(g_Wl + sel * 2048);
        ulonglong2* dh = (ulonglong2*)(smem + QSM_B_HI);
        ulonglong2* dl = (ulonglong2*)(smem + QSM_B_LO);
        #pragma unroll
        for (int it = 0; it < 2; it++) {
            int idx = it * 512 + t;
            dh[idx] = bh[idx];
            dl[idx] = bl[idx];
        }
    }
    __syncthreads();

    const int rg   = w >> 2;
    const int cg   = w & 3;
    const int g    = l >> 2;
    const int t2   = (l & 3) * 2;
    const int lx   = l & 7;
    const int bl15 = l & 15;
    const int jhi  = l >> 4;
    const int arow = rg * 32 + (l & 15);
    const int asw  = ((l & 15) & 7) << 4;

    float acc[2][4][4];
    #pragma unroll
    for (int m = 0; m < 2; m++)
        #pragma unroll
        for (int n = 0; n < 4; n++)
            #pragma unroll
            for (int q = 0; q < 4; q++) acc[m][n][q] = 0.f;

    #pragma unroll
    for (int ks = 0; ks < 4; ks++) {
        uint32_t ah[2][4], al[2][4];
        #pragma unroll
        for (int m = 0; m < 2; m++) {
            uint32_t aoff = (unsigned)(arow + m * 16) * 128 +
                            (((unsigned)(32 * ks + (l & 16))) ^ (unsigned)asw);
            ldmatrix_x4(ah[m], sbase + QSM_A_HI + aoff);
            ldmatrix_x4(al[m], sbase + QSM_A_LO + aoff);
        }
        uint32_t browoff = (unsigned)(16 * ks + bl15) * 256;
        #pragma unroll
        for (int np = 0; np < 2; np++) {
            uint32_t boff = ((unsigned)((cg * 4 + np * 2 + jhi) ^ lx)) << 4;
            uint32_t bh[4], blo[4];
            ldmatrix_x4t(bh,  sbase + QSM_B_HI + browoff + boff);
            ldmatrix_x4t(blo, sbase + QSM_B_LO + browoff + boff);
            #pragma unroll
            for (int m = 0; m < 2; m++) {
                mma16816(acc[m][np * 2],     ah[m], bh);
                mma16816(acc[m][np * 2 + 1], ah[m], bh + 2);
                mma16816(acc[m][np * 2],     al[m], bh);
                mma16816(acc[m][np * 2 + 1], al[m], bh + 2);
                mma16816(acc[m][np * 2],     ah[m], blo);
                mma16816(acc[m][np * 2 + 1], ah[m], blo + 2);
            }
        }
    }

    // epilogue: bias + store
    float2 bias[4];
    #pragma unroll
    for (int n = 0; n < 4; n++) {
        int col = cg * 32 + n * 8 + t2;
        bias[n] = make_float2(__ldg(Bv + col), __ldg(Bv + col + 1));
    }
    #pragma unroll
    for (int m = 0; m < 2; m++) {
        int row0 = m0 + rg * 32 + m * 16 + g;
        #pragma unroll
        for (int n = 0; n < 4; n++) {
            int col = cg * 32 + n * 8 + t2;
            if (row0 < NNODES)
                *(float2*)(out + (size_t)row0 * HD + col) =
                    make_float2(acc[m][n][0] + bias[n].x, acc[m][n][1] + bias[n].y);
            if (row0 + 8 < NNODES)
                *(float2*)(out + (size_t)(row0 + 8) * HD + col) =
                    make_float2(acc[m][n][2] + bias[n].x, acc[m][n][3] + bias[n].y);
        }
    }
}

// ---------------- K2: edge GEMM, BN=256 (all 8 heads), reg epilogue ---------
// 1024 threads / 32 warps; warp = 32 rows x 1 head (32 cols).
#define SM_A_HI 0
#define SM_A_LO 16384
#define SM_B_HI 32768
#define SM_B_LO 65536
#define SMEM_EDGE_TOTAL 98304

__global__ __launch_bounds__(1024, 1) void edge_kernel(
    const float* __restrict__ eattr, const int* __restrict__ eidx,
    const float* __restrict__ Eb, const float* __restrict__ Aw,
    float* __restrict__ outbuf)
{
    extern __shared__ char smem[];
    const uint32_t sbase = smem_u32(smem);
    const int t   = threadIdx.x;
    const int l   = t & 31;
    const int w   = t >> 5;
    const int m0  = blockIdx.x * 128;

    // ---- A tile: 128 edges x 64 K -> hi/lo bf16, swizzled (128B rows)
    #pragma unroll
    for (int it = 0; it < 2; it++) {
        int idx = it * 1024 + t;
        int row = idx >> 4;
        int c4  = (idx & 15) * 4;
        float4 v = __ldcs((const float4*)(eattr + (size_t)(m0 + row) * 64 + c4));
        unsigned int byte = (unsigned)row * 128 + (((unsigned)c4 * 2) ^ (((unsigned)row & 7) << 4));
        *(unsigned long long*)(smem + SM_A_HI + byte) = pack4_hi(v);
        *(unsigned long long*)(smem + SM_A_LO + byte) = pack4_hi(resid4(v));
    }
    // ---- B image copy (32KB each)
    {
        const ulonglong2* bh = (const ulonglong2*)g_Bh;
        const ulonglong2* bl = (const ulonglong2*)g_Bl;
        ulonglong2* dh = (ulonglong2*)(smem + SM_B_HI);
        ulonglong2* dl = (ulonglong2*)(smem + SM_B_LO);
        #pragma unroll
        for (int it = 0; it < 2; it++) {
            int idx = it * 1024 + t;
            dh[idx] = bh[idx];
            dl[idx] = bl[idx];
        }
    }
    __syncthreads();

    // ---- MMA: warp w -> rows 32*(w>>3)..+31, head (w&7)
    const int rg   = w >> 3;
    const int cg   = w & 7;
    const int g    = l >> 2;
    const int t2   = (l & 3) * 2;
    const int lx   = l & 7;
    const int bl15 = l & 15;
    const int jhi  = l >> 4;
    const int arow = rg * 32 + (l & 15);
    const int asw  = ((l & 15) & 7) << 4;

    float acc[2][4][4];
    #pragma unroll
    for (int m = 0; m < 2; m++)
        #pragma unroll
        for (int n = 0; n < 4; n++)
            #pragma unroll
            for (int q = 0; q < 4; q++) acc[m][n][q] = 0.f;

    #pragma unroll
    for (int ks = 0; ks < 4; ks++) {
        uint32_t ah[2][4], al[2][4];
        #pragma unroll
        for (int m = 0; m < 2; m++) {
            uint32_t aoff = (unsigned)(arow + m * 16) * 128 +
                            (((unsigned)(32 * ks + (l & 16))) ^ (unsigned)asw);
            ldmatrix_x4(ah[m], sbase + SM_A_HI + aoff);
            ldmatrix_x4(al[m], sbase + SM_A_LO + aoff);
        }
        uint32_t browoff = (unsigned)(16 * ks + bl15) * 512;   // 512B rows (256 cols)
        #pragma unroll
        for (int np = 0; np < 2; np++) {
            uint32_t boff = ((unsigned)((cg * 4 + np * 2 + jhi) ^ lx)) << 4;
            uint32_t bh[4], blo[4];
            ldmatrix_x4t(bh,  sbase + SM_B_HI + browoff + boff);
            ldmatrix_x4t(blo, sbase + SM_B_LO + browoff + boff);
            #pragma unroll
            for (int m = 0; m < 2; m++) {
                mma16816(acc[m][np * 2],     ah[m], bh);
                mma16816(acc[m][np * 2 + 1], ah[m], bh + 2);
                mma16816(acc[m][np * 2],     al[m], bh);
                mma16816(acc[m][np * 2 + 1], al[m], bh + 2);
                mma16816(acc[m][np * 2],     ah[m], blo);
                mma16816(acc[m][np * 2 + 1], ah[m], blo + 2);
            }
        }
    }

    // ---- epilogue (in registers) ----
    const int h    = cg;
    const int colK = h * 16;

    const float eb1a = __ldg(Eb + h * 32 + t2);
    const float eb1b = __ldg(Eb + h * 32 + t2 + 1);
    const float eb1c = __ldg(Eb + h * 32 + 8 + t2);
    const float eb1d = __ldg(Eb + h * 32 + 8 + t2 + 1);
    const float eb2a = __ldg(Eb + h * 32 + 16 + t2);
    const float eb2b = __ldg(Eb + h * 32 + 16 + t2 + 1);
    const float eb2c = __ldg(Eb + h * 32 + 24 + t2);
    const float eb2d = __ldg(Eb + h * 32 + 24 + t2 + 1);
    const float aw0 = __ldg(Aw + (t2)     * 8 + h);
    const float aw1 = __ldg(Aw + (t2 + 1) * 8 + h);
    const float aw8 = __ldg(Aw + (8 + t2)     * 8 + h);
    const float aw9 = __ldg(Aw + (8 + t2 + 1) * 8 + h);

    float apart[4];
    int   erow[4];
    #pragma unroll
    for (int r = 0; r < 4; r++) {
        const int m  = r >> 1;
        const int qh = r & 1;
        const int rowl = m * 16 + g + qh * 8;
        const int e  = m0 + rg * 32 + rowl;
        erow[r] = e;
        const int src = eidx[e];
        const int dst = eidx[NEDGES + e];
        const float* Krow = g_K + (size_t)src * HD + colK;
        const float* Qrow = g_Q + (size_t)dst * HD + colK;
        float* oEp = outbuf + (size_t)OUT_OE + (size_t)e * HD + colK;

        float a = 0.f;
        {
            float s1a = acc[m][0][qh * 2]     + eb1a;
            float s1b = acc[m][0][qh * 2 + 1] + eb1b;
            float s2a = acc[m][2][qh * 2]     + eb2a;
            float s2b = acc[m][2][qh * 2 + 1] + eb2b;
            float2 kv = *(const float2*)(Krow + t2);
            float2 qv = *(const float2*)(Qrow + t2);
            float p0 = s1a * s2a, p1 = s1b * s2b;
            float sc0 = copysignf(sqrt_approx(fabsf(p0)), p0) + kv.x + qv.x;
            float sc1 = copysignf(sqrt_approx(fabsf(p1)), p1) + kv.y + qv.y;
            __stcs((float2*)(oEp + t2), make_float2(sc0, sc1));
            a += sc0 * aw0 + sc1 * aw1;
        }
        {
            float s1a = acc[m][1][qh * 2]     + eb1c;
            float s1b = acc[m][1][qh * 2 + 1] + eb1d;
            float s2a = acc[m][3][qh * 2]     + eb2c;
            float s2b = acc[m][3][qh * 2 + 1] + eb2d;
            float2 kv = *(const float2*)(Krow + 8 + t2);
            float2 qv = *(const float2*)(Qrow + 8 + t2);
            float p0 = s1a * s2a, p1 = s1b * s2b;
            float sc0 = copysignf(sqrt_approx(fabsf(p0)), p0) + kv.x + qv.x;
            float sc1 = copysignf(sqrt_approx(fabsf(p1)), p1) + kv.y + qv.y;
            __stcs((float2*)(oEp + 8 + t2), make_float2(sc0, sc1));
            a += sc0 * aw8 + sc1 * aw9;
        }
        apart[r] = a;
    }

    #pragma unroll
    for (int r = 0; r < 4; r++) {
        apart[r] += __shfl_xor_sync(0xffffffffu, apart[r], 1);
        apart[r] += __shfl_xor_sync(0xffffffffu, apart[r], 2);
    }
    if ((l & 3) == 0) {
        #pragma unroll
        for (int r = 0; r < 4; r++) {
            float a = fminf(fmaxf(apart[r], -5.0f), 5.0f);
            g_w[(size_t)erow[r] * 8 + h] = expf(a);
        }
    }
}

// ---------------- K3: CSR build ---------------------------------------------
__global__ void zero_kernel()
{
    int i = blockIdx.x * blockDim.x + threadIdx.x;
    if (i < NNODES) g_deg[i] = 0;
}
__global__ void hist_kernel(const int* __restrict__ eidx)
{
    int e = blockIdx.x * blockDim.x + threadIdx.x;
    if (e < NEDGES) atomicAdd(&g_deg[eidx[NEDGES + e]], 1);
}
__global__ __launch_bounds__(SCAN_BLK) void scan1_kernel()
{
    __shared__ int warpsum[SCAN_BLK / 32];
    const int b = blockIdx.x, t = threadIdx.x;
    const int i = b * SCAN_BLK + t;
    int v = (i < NNODES) ? g_deg[i] : 0;
    int s = v;
    #pragma unroll
    for (int o = 1; o < 32; o <<= 1) {
        int u = __shfl_up_sync(0xffffffffu, s, o);
        if ((t & 31) >= o) s += u;
    }
    if ((t & 31) == 31) warpsum[t >> 5] = s;
    __syncthreads();
    if (t < SCAN_BLK / 32) {
        int ws = warpsum[t];
        #pragma unroll
        for (int o = 1; o < SCAN_BLK / 32; o <<= 1) {
            int u = __shfl_up_sync((1u << (SCAN_BLK / 32)) - 1u, ws, o);
            if (t >= o) ws += u;
        }
        warpsum[t] = ws;
    }
    __syncthreads();
    int excl = s - v + ((t >> 5) ? warpsum[(t >> 5) - 1] : 0);
    if (i < NNODES) g_off[i] = excl;
    if (t == SCAN_BLK - 1) g_bsum[b] = excl + v;
}
__global__ void scan2_kernel()
{
    __shared__ int ws[4];
    const int t = threadIdx.x;   // 128
    int v = (t < NSCB) ? g_bsum[t] : 0;
    int s = v;
    #pragma unroll
    for (int o = 1; o < 32; o <<= 1) {
        int u = __shfl_up_sync(0xffffffffu, s, o);
        if ((t & 31) >= o) s += u;
    }
    if ((t & 31) == 31) ws[t >> 5] = s;
    __syncthreads();
    if (t < 4) {
        int wv = ws[t];
        #pragma unroll
        for (int o = 1; o < 4; o <<= 1) {
            int u = __shfl_up_sync(0xfu, wv, o);
            if (t >= o) wv += u;
        }
        ws[t] = wv;
    }
    __syncthreads();
    int excl = s - v + ((t >> 5) ? ws[(t >> 5) - 1] : 0);
    if (t < NSCB) g_bpre[t] = excl;
    if (t == NSCB - 1) g_off[NNODES] = excl + v;
}
__global__ void scan3_kernel()
{
    int i = blockIdx.x * blockDim.x + threadIdx.x;
    if (i < NNODES) {
        int o = g_off[i] + g_bpre[i >> 8];
        g_off[i] = o;
        g_cursor[i] = o;
    }
}
__global__ void scatter_kernel(const int* __restrict__ eidx)
{
    int e = blockIdx.x * blockDim.x + threadIdx.x;
    if (e < NEDGES) {
        int dst = eidx[NEDGES + e];
        int p = atomicAdd(&g_cursor[dst], 1);
        g_csr[p] = make_int2(e, eidx[e]);
    }
}

// ---------------- K4: fused softmax + aggregation ---------------------------
__global__ __launch_bounds__(128) void node_kernel(
    const float* __restrict__ VeRow,
    const float* __restrict__ oE,
    float* __restrict__ n_out)
{
    __shared__ int2  stage[128];
    __shared__ float rowS[8][17];
    const int n = blockIdx.x;
    const int t = threadIdx.x;
    const int h = t >> 4, c = t & 15;
    const int beg = g_off[n], end = g_off[n + 1];

    float den = 0.f, accV = 0.f, accR = 0.f;
    for (int base = beg; base < end; base += 128) {
        int cnt = min(128, end - base);
        __syncthreads();
        if (t < cnt) stage[t] = g_csr[base + t];
        __syncthreads();
        #pragma unroll 4
        for (int i = 0; i < cnt; i++) {
            int e   = stage[i].x;
            int src = stage[i].y;
            float wv = g_w[(size_t)e * 8 + h];
            den  += wv;
            accV += wv * g_V[(size_t)src * HD + t];
            accR += wv * __ldcs(oE + (size_t)e * HD + t);
        }
    }
    float inv = 1.f / (den + 1e-16f);

    rowS[h][c] = accR * inv;
    __syncthreads();
    float r = 0.f;
    #pragma unroll
    for (int d = 0; d < 16; d++)
        r += rowS[h][d] * VeRow[d * HD + h * 16 + c];

    n_out[(size_t)n * HD + t] = accV * inv + r;
}

// ---------------- launch -----------------------------------------------------
extern "C" void kernel_launch(void* const* d_in, const int* in_sizes, int n_in,
                              void* d_out, int out_size)
{
    const float* x     = (const float*)d_in[0];
    const float* eattr = (const float*)d_in[1];
    const int*   eidx  = (const int*)  d_in[2];
    const float* Qw = (const float*)d_in[3];  const float* Qb = (const float*)d_in[4];
    const float* Kw = (const float*)d_in[5];  const float* Kb = (const float*)d_in[6];
    const float* Ew = (const float*)d_in[7];  const float* Eb = (const float*)d_in[8];
    const float* Vw = (const float*)d_in[9];  const float* Vb = (const float*)d_in[10];
    const float* Aw = (const float*)d_in[11]; const float* VeRow = (const float*)d_in[12];
    float* out = (float*)d_out;

    cudaFuncSetAttribute(edge_kernel, cudaFuncAttributeMaxDynamicSharedMemorySize,
                         SMEM_EDGE_TOTAL);
    cudaFuncSetAttribute(qkv_kernel, cudaFuncAttributeMaxDynamicSharedMemorySize,
                         SMEM_QKV_TOTAL);

    bprep_kernel<<<4, 256>>>(Ew);                                           // 1
    wprep_kernel<<<3, 256>>>(Qw, Kw, Vw);                                   // 2
    qkv_kernel<<<dim3((NNODES + 127) / 128, 3), 512, SMEM_QKV_TOTAL>>>(x, Qb, Kb, Vb); // 3
    edge_kernel<<<NEDGES / 128, 1024, SMEM_EDGE_TOTAL>>>(eattr, eidx, Eb, Aw, out);    // 4 (profiled)
    zero_kernel<<<(NNODES + 255) / 256, 256>>>();                           // 5
    hist_kernel<<<(NEDGES + 255) / 256, 256>>>(eidx);                       // 6
    scan1_kernel<<<NSCB, SCAN_BLK>>>();                                     // 7
    scan2_kernel<<<1, 128>>>();                                             // 8
    scan3_kernel<<<(NNODES + 255) / 256, 256>>>();                          // 9
    scatter_kernel<<<(NEDGES + 255) / 256, 256>>>(eidx);                    // 10
    node_kernel<<<NNODES, 128>>>(VeRow, out + OUT_OE, out);                 // 11
}